// round 14
// baseline (speedup 1.0000x reference)
#include <cuda_runtime.h>
#include <cuda_bf16.h>
#include <cuda_fp16.h>
#include <cstdint>

// ---------------- problem constants ----------------
#define C64   64
#define NBINS 32
#define NSP   32768
#define SEGS  (NSP * NBINS)        // 1048576
#define INF   2048                 // IN = C*NBINS
#define HID   1024
#define BN_EPS 1e-3f

// ---------------- device scratch (static; no allocs) ----------------
__device__ __align__(16) __half g_sums[(size_t)SEGS * C64];          // 128 MB half accum
__device__ __align__(16) float g_cnt[SEGS];                          // 4 MB
__device__ __align__(16) __half g_Ah[(size_t)NSP * INF];             // 128 MB fp16(A)
__device__ __align__(16) __half g_Wh[(size_t)HID * INF];             // 4 MB fp16(w1)
__device__ __align__(16) __half g_x1h[(size_t)NSP * HID];            // 64 MB fp16(x1)
__device__ __align__(16) __half g_W2h[(size_t)C64 * HID];            // 128 KB fp16(w2)
__device__ __align__(16) float g_x2[(size_t)NSP * C64];              // 8 MB
__device__ __align__(16) float g_mask[NSP];
__device__ __align__(16) float g_scale0[C64], g_bias0[C64];
__device__ __align__(16) float g_scale1[HID], g_bias1[HID];
__device__ __align__(16) float g_scale2[C64], g_bias2[C64];

#define ACC_N (44 + 2 * HID + 2 * C64 + 1)
__device__ __align__(16) float g_accbuf[ACC_N];
#define ACC0  (g_accbuf)
#define S1ACC (g_accbuf + 44)
#define Q1ACC (g_accbuf + 44 + HID)
#define S2ACC (g_accbuf + 44 + 2 * HID)
#define Q2ACC (g_accbuf + 44 + 2 * HID + C64)
#define NACC  (g_accbuf + 44 + 2 * HID + 2 * C64)

// ---------------- PTX helpers (sm_80-compatible only) ----------------
__device__ __forceinline__ uint32_t smem_u32(const void* p) {
    uint32_t a;
    asm("{ .reg .u64 t; cvta.to.shared.u64 t, %1; cvt.u32.u64 %0, t; }" : "=r"(a) : "l"(p));
    return a;
}
__device__ __forceinline__ void cpasync16(uint32_t dst, const void* src) {
    asm volatile("cp.async.cg.shared.global [%0], [%1], 16;" :: "r"(dst), "l"(src));
}
#define CP_COMMIT() asm volatile("cp.async.commit_group;")
#define CP_WAIT(n)  asm volatile("cp.async.wait_group %0;" :: "n"(n))

#define LDSM_X4(r, addr) \
    asm volatile("ldmatrix.sync.aligned.m8n8.x4.shared.b16 {%0,%1,%2,%3}, [%4];" \
        : "=r"((r)[0]), "=r"((r)[1]), "=r"((r)[2]), "=r"((r)[3]) : "r"(addr))

__device__ __forceinline__ void mma16816h(float* c, const uint32_t* a, uint32_t b0, uint32_t b1) {
    asm volatile(
        "mma.sync.aligned.m16n8k16.row.col.f32.f16.f16.f32 "
        "{%0,%1,%2,%3}, {%4,%5,%6,%7}, {%8,%9}, {%0,%1,%2,%3};"
        : "+f"(c[0]), "+f"(c[1]), "+f"(c[2]), "+f"(c[3])
        : "r"(a[0]), "r"(a[1]), "r"(a[2]), "r"(a[3]), "r"(b0), "r"(b1));
}

__device__ __forceinline__ uint32_t h2_bits(__half2 h) {
    uint32_t u;
    memcpy(&u, &h, 4);
    return u;
}

// ---------------- K1: point feature moments (float4-vectorized, 4 pts/iter) ----------------
__global__ void pstats_kernel(const float* __restrict__ points, int n_pts) {
    float s[44];
#pragma unroll
    for (int i = 0; i < 44; i++) s[i] = 0.f;
    int gid = blockIdx.x * blockDim.x + threadIdx.x;
    int stride = gridDim.x * blockDim.x;
    int nchunk = n_pts >> 2;
    for (int ch = gid; ch < nchunk; ch += stride) {
        const float4* p4 = (const float4*)(points + (size_t)ch * 36);
        float f36[36];
#pragma unroll
        for (int j = 0; j < 9; j++) {
            float4 v = __ldg(&p4[j]);
            f36[4 * j] = v.x; f36[4 * j + 1] = v.y;
            f36[4 * j + 2] = v.z; f36[4 * j + 3] = v.w;
        }
#pragma unroll
        for (int k = 0; k < 4; k++) {
            const float* f = f36 + 9 * k + 1;
#pragma unroll
            for (int j = 0; j < 8; j++) s[j] += f[j];
            int idx = 8;
#pragma unroll
            for (int j = 0; j < 8; j++)
#pragma unroll
                for (int k2 = j; k2 < 8; k2++) s[idx++] += f[j] * f[k2];
        }
    }
    for (int p = (nchunk << 2) + gid; p < n_pts; p += stride) {
        const float* pt = points + (size_t)p * 9;
        float f[8];
#pragma unroll
        for (int j = 0; j < 8; j++) f[j] = __ldg(&pt[1 + j]);
#pragma unroll
        for (int j = 0; j < 8; j++) s[j] += f[j];
        int idx = 8;
#pragma unroll
        for (int j = 0; j < 8; j++)
#pragma unroll
            for (int k = j; k < 8; k++) s[idx++] += f[j] * f[k];
    }
#pragma unroll
    for (int i = 0; i < 44; i++)
#pragma unroll
        for (int o = 16; o > 0; o >>= 1) s[i] += __shfl_down_sync(0xffffffffu, s[i], o);
    __shared__ float part[8][44];
    int lane = threadIdx.x & 31, w = threadIdx.x >> 5;
    if (lane == 0)
#pragma unroll
        for (int i = 0; i < 44; i++) part[w][i] = s[i];
    __syncthreads();
    if (threadIdx.x < 44) {
        float t = 0.f;
#pragma unroll
        for (int w2 = 0; w2 < 8; w2++) t += part[w2][threadIdx.x];
        atomicAdd(&ACC0[threadIdx.x], t);
    }
}

// ---------------- K2: fold BN0 ----------------
__global__ void fin0_kernel(const float* __restrict__ lin0_w,
                            const float* __restrict__ g0,
                            const float* __restrict__ b0, float inv_n) {
    int c = threadIdx.x;
    float Ef[8];
#pragma unroll
    for (int j = 0; j < 8; j++) Ef[j] = ACC0[j] * inv_n;
    float w[8];
#pragma unroll
    for (int j = 0; j < 8; j++) w[j] = lin0_w[c * 8 + j];
    float m0 = 0.f;
#pragma unroll
    for (int j = 0; j < 8; j++) m0 += w[j] * Ef[j];
    float e2 = 0.f;
    int idx = 8;
#pragma unroll
    for (int j = 0; j < 8; j++)
#pragma unroll
        for (int k = j; k < 8; k++) {
            float t = w[j] * w[k] * (ACC0[idx] * inv_n);
            e2 += (k == j) ? t : 2.f * t;
            idx++;
        }
    float v0 = fmaxf(e2 - m0 * m0, 0.f);
    float scl = g0[c] * rsqrtf(v0 + BN_EPS);
    g_scale0[c] = scl;
    g_bias0[c] = b0[c] - m0 * scl;
}

// ---------------- K3: per-point compute + half2 scatter-add (float2 weights, 2-pt unroll) ----------------
__global__ void scatter_kernel(const float* __restrict__ points,
                               const int* __restrict__ pmc,
                               const float* __restrict__ lin0_w, int n_pts) {
    __shared__ float2 Wt2[8][32];     // Wt2[j][lane] = weights for channels (2*lane, 2*lane+1)
    __shared__ float2 sc2[32], bi2[32];
    int tid = threadIdx.x;
    if (tid < 32) {
        sc2[tid] = make_float2(g_scale0[2 * tid], g_scale0[2 * tid + 1]);
        bi2[tid] = make_float2(g_bias0[2 * tid], g_bias0[2 * tid + 1]);
    }
    for (int i = tid; i < 256; i += blockDim.x) {
        int lane32 = i & 31, j = i >> 5;
        Wt2[j][lane32] = make_float2(lin0_w[(2 * lane32) * 8 + j],
                                     lin0_w[(2 * lane32 + 1) * 8 + j]);
    }
    __syncthreads();
    int lane = tid & 31;
    int gw = blockIdx.x * (blockDim.x >> 5) + (tid >> 5);
    int nw = gridDim.x * (blockDim.x >> 5);
    float2 sc = sc2[lane], bi = bi2[lane];
    float2 W[8];
#pragma unroll
    for (int j = 0; j < 8; j++) W[j] = Wt2[j][lane];

    int p = gw;
    for (; p + nw < n_pts; p += 2 * nw) {
        int pillarA = __ldg(&pmc[p]);
        int pillarB = __ldg(&pmc[p + nw]);
        const float* ptA = points + (size_t)p * 9;
        const float* ptB = points + (size_t)(p + nw) * 9;
        float fA[8], fB[8];
#pragma unroll
        for (int j = 0; j < 8; j++) { fA[j] = __ldg(&ptA[1 + j]); fB[j] = __ldg(&ptB[1 + j]); }
        int zbA = min(max((int)floorf((fA[5] + 4.0f) * 4.0f), 0), NBINS - 1);
        int zbB = min(max((int)floorf((fB[5] + 4.0f) * 4.0f), 0), NBINS - 1);
        float a0 = W[0].x * fA[0], a1 = W[0].y * fA[0];
        float b0 = W[0].x * fB[0], b1 = W[0].y * fB[0];
#pragma unroll
        for (int j = 1; j < 8; j++) {
            a0 = fmaf(W[j].x, fA[j], a0); a1 = fmaf(W[j].y, fA[j], a1);
            b0 = fmaf(W[j].x, fB[j], b0); b1 = fmaf(W[j].y, fB[j], b1);
        }
        a0 = fmaxf(fmaf(a0, sc.x, bi.x), 0.f); a1 = fmaxf(fmaf(a1, sc.y, bi.y), 0.f);
        b0 = fmaxf(fmaf(b0, sc.x, bi.x), 0.f); b1 = fmaxf(fmaf(b1, sc.y, bi.y), 0.f);
        size_t baseA = ((size_t)pillarA * NBINS + zbA) * C64 + lane * 2;
        size_t baseB = ((size_t)pillarB * NBINS + zbB) * C64 + lane * 2;
        atomicAdd((__half2*)(g_sums + baseA), __floats2half2_rn(a0, a1));
        atomicAdd((__half2*)(g_sums + baseB), __floats2half2_rn(b0, b1));
        if (lane == 0) {
            atomicAdd(&g_cnt[(size_t)pillarA * NBINS + zbA], 1.0f);
            atomicAdd(&g_cnt[(size_t)pillarB * NBINS + zbB], 1.0f);
        }
    }
    for (; p < n_pts; p += nw) {
        int pillar = __ldg(&pmc[p]);
        const float* pt = points + (size_t)p * 9;
        float f[8];
#pragma unroll
        for (int j = 0; j < 8; j++) f[j] = __ldg(&pt[1 + j]);
        int zb = min(max((int)floorf((f[5] + 4.0f) * 4.0f), 0), NBINS - 1);
        float v0 = W[0].x * f[0], v1 = W[0].y * f[0];
#pragma unroll
        for (int j = 1; j < 8; j++) {
            v0 = fmaf(W[j].x, f[j], v0);
            v1 = fmaf(W[j].y, f[j], v1);
        }
        v0 = fmaxf(fmaf(v0, sc.x, bi.x), 0.f);
        v1 = fmaxf(fmaf(v1, sc.y, bi.y), 0.f);
        size_t base = ((size_t)pillar * NBINS + zb) * C64 + lane * 2;
        atomicAdd((__half2*)(g_sums + base), __floats2half2_rn(v0, v1));
        if (lane == 0) atomicAdd(&g_cnt[(size_t)pillar * NBINS + zb], 1.0f);
    }
}

// ---------------- K4: means (+sparse_feat) -> fp16 A; skip empty reads ----------------
__global__ void normsplit_kernel(const float* __restrict__ sparse_feat) {
    size_t i4 = (size_t)blockIdx.x * blockDim.x + threadIdx.x;  // 4 channels per thread
    if (i4 >= (size_t)SEGS * C64 / 4) return;
    size_t seg = i4 >> 4;
    float c = g_cnt[seg];
    float4 v = make_float4(0.f, 0.f, 0.f, 0.f);
    if (c > 0.5f) {
        uint2 raw = ((const uint2*)g_sums)[i4];
        __half2 h0, h1;
        memcpy(&h0, &raw.x, 4);
        memcpy(&h1, &raw.y, 4);
        float2 a = __half22float2(h0);
        float2 b = __half22float2(h1);
        float inv = 1.0f / c;
        int pillar = (int)(seg >> 5);
        int cc = (int)(i4 & 15) * 4;
        float4 sf = *(const float4*)(sparse_feat + (size_t)pillar * C64 + cc);
        v.x = fmaf(a.x, inv, sf.x);
        v.y = fmaf(a.y, inv, sf.y);
        v.z = fmaf(b.x, inv, sf.z);
        v.w = fmaf(b.y, inv, sf.w);
    }
    uint32_t p0 = h2_bits(__floats2half2_rn(v.x, v.y));
    uint32_t p1 = h2_bits(__floats2half2_rn(v.z, v.w));
    ((uint2*)g_Ah)[i4] = make_uint2(p0, p1);
}

// ---------------- K4b: round w1 AND w2 to fp16 (merged) ----------------
#define W1_Q (HID * INF / 4)
#define W2_Q (C64 * HID / 4)
__global__ void wconv_kernel(const float* __restrict__ w1, const float* __restrict__ w2) {
    int i4 = blockIdx.x * blockDim.x + threadIdx.x;
    if (i4 < W1_Q) {
        float4 v = ((const float4*)w1)[i4];
        uint32_t p0 = h2_bits(__floats2half2_rn(v.x, v.y));
        uint32_t p1 = h2_bits(__floats2half2_rn(v.z, v.w));
        ((uint2*)g_Wh)[i4] = make_uint2(p0, p1);
    } else if (i4 < W1_Q + W2_Q) {
        int j4 = i4 - W1_Q;
        float4 v = ((const float4*)w2)[j4];
        uint32_t p0 = h2_bits(__floats2half2_rn(v.x, v.y));
        uint32_t p1 = h2_bits(__floats2half2_rn(v.z, v.w));
        ((uint2*)g_W2h)[j4] = make_uint2(p0, p1);
    }
}

// ---------------- K5: occupied mask + n ----------------
__global__ void mask_kernel() {
    int p = blockIdx.x * (blockDim.x >> 5) + (threadIdx.x >> 5);
    int lane = threadIdx.x & 31;
    if (p >= NSP) return;
    float c = g_cnt[(size_t)p * NBINS + lane];
    unsigned bal = __ballot_sync(0xffffffffu, c > 0.5f);
    if (lane == 0) {
        float mk = (__popc(bal) >= 2) ? 1.f : 0.f;
        g_mask[p] = mk;
        atomicAdd(NACC, mk);
    }
}

// ---------------- K6: GEMM1 via mma.sync fp16, single term ----------------
#define KC     32
#define PITCH  80
#define STG_A  (128 * PITCH)         // 10240
#define STG_W  (256 * PITCH)         // 20480
#define STG_BYTES (STG_A + STG_W)    // 30720
#define SMEM_G1 (4 * STG_BYTES)      // 122880
#define NST    64

__device__ __forceinline__ void g1_load_stage(uint32_t sb, int s, int m0, int n0, int tid) {
    if (s < NST) {
        int k0 = s * KC;
        uint32_t buf = sb + (uint32_t)(s & 3) * STG_BYTES;
#pragma unroll
        for (int i = 0; i < 2; i++) {
            int id = tid + i * 256;
            int row = id >> 2, c = id & 3;
            cpasync16(buf + row * PITCH + c * 16,
                      g_Ah + (size_t)(m0 + row) * INF + k0 + c * 8);
        }
#pragma unroll
        for (int i = 0; i < 4; i++) {
            int id = tid + i * 256;
            int row = id >> 2, c = id & 3;
            cpasync16(buf + STG_A + row * PITCH + c * 16,
                      g_Wh + (size_t)(n0 + row) * INF + k0 + c * 8);
        }
    }
    CP_COMMIT();
}

__global__ __launch_bounds__(256, 1) void gemm1_mma_kernel() {
    extern __shared__ char smem[];
    uint32_t sb = smem_u32(smem);
    const int tid = threadIdx.x;
    const int w = tid >> 5, l = tid & 31;
    const int m0 = blockIdx.y * 128;
    const int n0 = blockIdx.x * 256;
    const int wm = (w >> 2) * 64;
    const int wn = (w & 3) * 64;

    float acc[4][8][4];
#pragma unroll
    for (int i = 0; i < 4; i++)
#pragma unroll
        for (int j = 0; j < 8; j++)
#pragma unroll
            for (int k = 0; k < 4; k++) acc[i][j][k] = 0.f;

    g1_load_stage(sb, 0, m0, n0, tid);
    g1_load_stage(sb, 1, m0, n0, tid);
    g1_load_stage(sb, 2, m0, n0, tid);

    const uint32_t aoff = (uint32_t)((wm + (l & 15)) * PITCH + ((l >> 4) & 1) * 16);
    const uint32_t bhoff = (uint32_t)(STG_A + (wn + (l & 15)) * PITCH + ((l >> 4) & 1) * 16);

#pragma unroll 1
    for (int s = 0; s < NST; s++) {
        CP_WAIT(2);
        __syncthreads();
        g1_load_stage(sb, s + 3, m0, n0, tid);
        uint32_t buf = sb + (uint32_t)(s & 3) * STG_BYTES;
#pragma unroll
        for (int h = 0; h < 2; h++) {
            uint32_t af[4][4], bh[4][4];
#pragma unroll
            for (int mt = 0; mt < 4; mt++)
                LDSM_X4(af[mt], buf + aoff + mt * 16 * PITCH + h * 32);
#pragma unroll
            for (int bt = 0; bt < 4; bt++)
                LDSM_X4(bh[bt], buf + bhoff + bt * 16 * PITCH + h * 32);
#pragma unroll
            for (int mt = 0; mt < 4; mt++)
#pragma unroll
                for (int bt = 0; bt < 4; bt++) {
                    mma16816h(acc[mt][bt * 2 + 0], af[mt], bh[bt][0], bh[bt][2]);
                    mma16816h(acc[mt][bt * 2 + 1], af[mt], bh[bt][1], bh[bt][3]);
                }
        }
    }

    // epilogue: fp16 x1 store + fused masked column stats (BN1, f32)
    const int r0 = l >> 2;
    const int cc = (l & 3) * 2;
    float msk[4][2];
#pragma unroll
    for (int mt = 0; mt < 4; mt++) {
        msk[mt][0] = g_mask[m0 + wm + mt * 16 + r0];
        msk[mt][1] = g_mask[m0 + wm + mt * 16 + r0 + 8];
    }
#pragma unroll
    for (int nt = 0; nt < 8; nt++) {
        float s0 = 0.f, q0 = 0.f, s1 = 0.f, q1 = 0.f;
#pragma unroll
        for (int mt = 0; mt < 4; mt++) {
            size_t row = (size_t)(m0 + wm + mt * 16 + r0);
            size_t col = (size_t)(n0 + wn + nt * 8 + cc);
            *(__half2*)(g_x1h + row * HID + col) =
                __floats2half2_rn(acc[mt][nt][0], acc[mt][nt][1]);
            *(__half2*)(g_x1h + (row + 8) * HID + col) =
                __floats2half2_rn(acc[mt][nt][2], acc[mt][nt][3]);
            float a0 = acc[mt][nt][0], a1 = acc[mt][nt][1];
            float a2 = acc[mt][nt][2], a3 = acc[mt][nt][3];
            s0 += msk[mt][0] * a0 + msk[mt][1] * a2;
            q0 += msk[mt][0] * a0 * a0 + msk[mt][1] * a2 * a2;
            s1 += msk[mt][0] * a1 + msk[mt][1] * a3;
            q1 += msk[mt][0] * a1 * a1 + msk[mt][1] * a3 * a3;
        }
#pragma unroll
        for (int o = 4; o <= 16; o <<= 1) {
            s0 += __shfl_xor_sync(0xffffffffu, s0, o);
            q0 += __shfl_xor_sync(0xffffffffu, q0, o);
            s1 += __shfl_xor_sync(0xffffffffu, s1, o);
            q1 += __shfl_xor_sync(0xffffffffu, q1, o);
        }
        if (r0 == 0) {
            int col = n0 + wn + nt * 8 + cc;
            atomicAdd(&S1ACC[col], s0);
            atomicAdd(&Q1ACC[col], q0);
            atomicAdd(&S1ACC[col + 1], s1);
            atomicAdd(&Q1ACC[col + 1], q1);
        }
    }
}

__global__ void fin1_kernel(const float* __restrict__ g1, const float* __restrict__ b1) {
    int c = threadIdx.x;
    float n = fmaxf(*NACC, 1.f);
    float m = S1ACC[c] / n;
    float v = fmaxf(Q1ACC[c] / n - m * m, 0.f);
    float scl = g1[c] * rsqrtf(v + BN_EPS);
    g_scale1[c] = scl;
    g_bias1[c] = b1[c] - m * scl;
}

// ---------------- K8: GEMM2 via mma.sync fp16 + fused BN2 stats ----------------
#define G2_PITCH  80
#define G2_STG_A  (256 * G2_PITCH)    // 20480
#define G2_BPITCH 2064
#define G2_SMEM_B (C64 * G2_BPITCH)   // 132096
#define G2_SMEM   (2 * G2_STG_A + G2_SMEM_B)  // 173056
#define G2_NST    (HID / KC)          // 32

__global__ __launch_bounds__(256, 1) void gemm2_mma_kernel() {
    extern __shared__ char smem[];
    uint32_t sb = smem_u32(smem);
    uint32_t sbB = sb + 2 * G2_STG_A;
    const int tid = threadIdx.x;
    const int w = tid >> 5, l = tid & 31;
    const int m0 = blockIdx.x * 256;
    const int wm = (w >> 1) * 64;
    const int wn = (w & 1) * 32;

#pragma unroll
    for (int i = 0; i < 32; i++) {
        int id = tid + i * 256;
        int row = id >> 7, c = id & 127;
        cpasync16(sbB + row * G2_BPITCH + c * 16, g_W2h + (size_t)row * HID + c * 8);
    }
    CP_COMMIT();

    float acc[4][4][4];
#pragma unroll
    for (int i = 0; i < 4; i++)
#pragma unroll
        for (int j = 0; j < 4; j++)
#pragma unroll
            for (int k = 0; k < 4; k++) acc[i][j][k] = 0.f;

    const size_t arow = (size_t)(m0 + tid);
    uint4 areg[4];
#pragma unroll
    for (int c = 0; c < 4; c++)
        areg[c] = *(const uint4*)(g_x1h + arow * HID + c * 8);

    const uint32_t aoff = (uint32_t)((wm + (l & 15)) * G2_PITCH + ((l >> 4) & 1) * 16);
    const uint32_t boff = (uint32_t)((wn + (l & 15)) * G2_BPITCH + ((l >> 4) & 1) * 16);

    CP_WAIT(0);
    __syncthreads();

#pragma unroll 1
    for (int s = 0; s < G2_NST; s++) {
        int kt = s * KC;
        uint32_t buf = sb + (uint32_t)(s & 1) * G2_STG_A;
#pragma unroll
        for (int c = 0; c < 4; c++) {
            int kg = kt + c * 8;
            float4 sc0 = *(const float4*)(g_scale1 + kg);
            float4 sc1 = *(const float4*)(g_scale1 + kg + 4);
            float4 bi0 = *(const float4*)(g_bias1 + kg);
            float4 bi1 = *(const float4*)(g_bias1 + kg + 4);
            const uint32_t* hp = (const uint32_t*)&areg[c];
            uint4 outv;
            uint32_t* op = (uint32_t*)&outv;
            float scs[8] = {sc0.x, sc0.y, sc0.z, sc0.w, sc1.x, sc1.y, sc1.z, sc1.w};
            float bis[8] = {bi0.x, bi0.y, bi0.z, bi0.w, bi1.x, bi1.y, bi1.z, bi1.w};
#pragma unroll
            for (int q = 0; q < 4; q++) {
                __half2 hv;
                memcpy(&hv, &hp[q], 4);
                float2 f = __half22float2(hv);
                f.x = fmaxf(fmaf(f.x, scs[2 * q], bis[2 * q]), 0.f);
                f.y = fmaxf(fmaf(f.y, scs[2 * q + 1], bis[2 * q + 1]), 0.f);
                op[q] = h2_bits(__floats2half2_rn(f.x, f.y));
            }
            *(uint4*)(smem + (size_t)(s & 1) * G2_STG_A + tid * G2_PITCH + c * 16) = outv;
        }
        __syncthreads();
        if (s + 1 < G2_NST) {
#pragma unroll
            for (int c = 0; c < 4; c++)
                areg[c] = *(const uint4*)(g_x1h + arow * HID + (s + 1) * KC + c * 8);
        }
#pragma unroll
        for (int h = 0; h < 2; h++) {
            uint32_t af[4][4], bf[2][4];
#pragma unroll
            for (int mt = 0; mt < 4; mt++)
                LDSM_X4(af[mt], buf + aoff + mt * 16 * G2_PITCH + h * 32);
#pragma unroll
            for (int bt = 0; bt < 2; bt++)
                LDSM_X4(bf[bt], sbB + boff + bt * 16 * G2_BPITCH + s * 64 + h * 32);
#pragma unroll
            for (int mt = 0; mt < 4; mt++)
#pragma unroll
                for (int bt = 0; bt < 2; bt++) {
                    mma16816h(acc[mt][bt * 2 + 0], af[mt], bf[bt][0], bf[bt][2]);
                    mma16816h(acc[mt][bt * 2 + 1], af[mt], bf[bt][1], bf[bt][3]);
                }
        }
        __syncthreads();
    }

    const int r0 = l >> 2;
    const int cc = (l & 3) * 2;
    float msk[4][2];
#pragma unroll
    for (int mt = 0; mt < 4; mt++) {
        msk[mt][0] = g_mask[m0 + wm + mt * 16 + r0];
        msk[mt][1] = g_mask[m0 + wm + mt * 16 + r0 + 8];
    }
#pragma unroll
    for (int nt = 0; nt < 4; nt++) {
        float s0 = 0.f, q0 = 0.f, s1 = 0.f, q1 = 0.f;
#pragma unroll
        for (int mt = 0; mt < 4; mt++) {
            size_t row = (size_t)(m0 + wm + mt * 16 + r0);
            size_t col = (size_t)(wn + nt * 8 + cc);
            *(float2*)(g_x2 + row * C64 + col) =
                make_float2(acc[mt][nt][0], acc[mt][nt][1]);
            *(float2*)(g_x2 + (row + 8) * C64 + col) =
                make_float2(acc[mt][nt][2], acc[mt][nt][3]);
            float a0 = acc[mt][nt][0], a1 = acc[mt][nt][1];
            float a2 = acc[mt][nt][2], a3 = acc[mt][nt][3];
            s0 += msk[mt][0] * a0 + msk[mt][1] * a2;
            q0 += msk[mt][0] * a0 * a0 + msk[mt][1] * a2 * a2;
            s1 += msk[mt][0] * a1 + msk[mt][1] * a3;
            q1 += msk[mt][0] * a1 * a1 + msk[mt][1] * a3 * a3;
        }
#pragma unroll
        for (int o = 4; o <= 16; o <<= 1) {
            s0 += __shfl_xor_sync(0xffffffffu, s0, o);
            q0 += __shfl_xor_sync(0xffffffffu, q0, o);
            s1 += __shfl_xor_sync(0xffffffffu, s1, o);
            q1 += __shfl_xor_sync(0xffffffffu, q1, o);
        }
        if (r0 == 0) {
            int col = wn + nt * 8 + cc;
            atomicAdd(&S2ACC[col], s0);
            atomicAdd(&Q2ACC[col], q0);
            atomicAdd(&S2ACC[col + 1], s1);
            atomicAdd(&Q2ACC[col + 1], q1);
        }
    }
}

__global__ void fin2_kernel(const float* __restrict__ g2, const float* __restrict__ b2) {
    int c = threadIdx.x;
    float n = fmaxf(*NACC, 1.f);
    float m = S2ACC[c] / n;
    float v = fmaxf(Q2ACC[c] / n - m * m, 0.f);
    float scl = g2[c] * rsqrtf(v + BN_EPS);
    g_scale2[c] = scl;
    g_bias2[c] = b2[c] - m * scl;
}

// ---------------- K10: output ----------------
__global__ void final_kernel(const float* __restrict__ sparse_feat, float* __restrict__ out) {
    int i = blockIdx.x * blockDim.x + threadIdx.x;
    if (i < NSP * C64) {
        int p = i >> 6, c = i & 63;
        out[i] = sparse_feat[i] +
                 g_mask[p] * fmaxf(fmaf(g_scale2[c], g_x2[i], g_bias2[c]), 0.f);
    }
}

// ---------------- launch ----------------
extern "C" void kernel_launch(void* const* d_in, const int* in_sizes, int n_in,
                              void* d_out, int out_size) {
    const float* points = (const float*)d_in[0];
    const float* sparse = (const float*)d_in[1];
    const float* lin0_w = (const float*)d_in[2];
    const float* bn0_g = (const float*)d_in[3];
    const float* bn0_b = (const float*)d_in[4];
    const float* w1 = (const float*)d_in[5];
    const float* bn1_g = (const float*)d_in[6];
    const float* bn1_b = (const float*)d_in[7];
    const float* w2 = (const float*)d_in[8];
    const float* bn2_g = (const float*)d_in[9];
    const float* bn2_b = (const float*)d_in[10];
    const int* pmc = (const int*)d_in[11];
    float* out = (float*)d_out;
    int n_pts = in_sizes[0] / 9;

    cudaFuncSetAttribute(gemm1_mma_kernel, cudaFuncAttributeMaxDynamicSharedMemorySize, SMEM_G1);
    cudaFuncSetAttribute(gemm2_mma_kernel, cudaFuncAttributeMaxDynamicSharedMemorySize, G2_SMEM);

    void *p_sums, *p_cnt, *p_acc;
    cudaGetSymbolAddress(&p_sums, g_sums);
    cudaGetSymbolAddress(&p_cnt, g_cnt);
    cudaGetSymbolAddress(&p_acc, g_accbuf);
    cudaMemsetAsync(p_sums, 0, sizeof(g_sums));
    cudaMemsetAsync(p_cnt, 0, sizeof(g_cnt));
    cudaMemsetAsync(p_acc, 0, sizeof(g_accbuf));

    pstats_kernel<<<256, 256>>>(points, n_pts);
    fin0_kernel<<<1, 64>>>(lin0_w, bn0_g, bn0_b, 1.0f / (float)n_pts);
    wconv_kernel<<<(W1_Q + W2_Q + 255) / 256, 256>>>(w1, w2);
    scatter_kernel<<<1024, 256>>>(points, pmc, lin0_w, n_pts);
    normsplit_kernel<<<(SEGS * C64 / 4) / 256, 256>>>(sparse);
    mask_kernel<<<NSP / 8, 256>>>();
    gemm1_mma_kernel<<<dim3(HID / 256, NSP / 128), 256, SMEM_G1>>>();
    fin1_kernel<<<1, HID>>>(bn1_g, bn1_b);
    gemm2_mma_kernel<<<NSP / 256, 256, G2_SMEM>>>();
    fin2_kernel<<<1, 64>>>(bn2_g, bn2_b);
    final_kernel<<<(NSP * C64) / 256, 256>>>(sparse, out);
}

// round 15
// speedup vs baseline: 1.0047x; 1.0047x over previous
#include <cuda_runtime.h>
#include <cuda_bf16.h>
#include <cuda_fp16.h>
#include <cstdint>

// ---------------- problem constants ----------------
#define C64   64
#define NBINS 32
#define NSP   32768
#define SEGS  (NSP * NBINS)        // 1048576
#define INF   2048                 // IN = C*NBINS
#define HID   1024
#define BN_EPS 1e-3f

// ---------------- device scratch (static; no allocs) ----------------
__device__ __align__(16) __half g_sums[(size_t)SEGS * C64];          // 128 MB half accum
__device__ __align__(16) float g_cnt[SEGS];                          // 4 MB
__device__ __align__(16) __half g_Ah[(size_t)NSP * INF];             // 128 MB fp16(A)
__device__ __align__(16) __half g_Wh[(size_t)HID * INF];             // 4 MB fp16(w1)
__device__ __align__(16) __half g_x1h[(size_t)NSP * HID];            // 64 MB fp16(x1)
__device__ __align__(16) __half g_W2h[(size_t)C64 * HID];            // 128 KB fp16(w2)
__device__ __align__(16) float g_x2[(size_t)NSP * C64];              // 8 MB
__device__ __align__(16) float g_mask[NSP];
__device__ __align__(16) float g_scale0[C64], g_bias0[C64];
__device__ __align__(16) float g_scale1[HID], g_bias1[HID];
__device__ __align__(16) float g_scale2[C64], g_bias2[C64];

#define ACC_N (44 + 2 * HID + 2 * C64 + 1)
__device__ __align__(16) float g_accbuf[ACC_N];
#define ACC0  (g_accbuf)
#define S1ACC (g_accbuf + 44)
#define Q1ACC (g_accbuf + 44 + HID)
#define S2ACC (g_accbuf + 44 + 2 * HID)
#define Q2ACC (g_accbuf + 44 + 2 * HID + C64)
#define NACC  (g_accbuf + 44 + 2 * HID + 2 * C64)

// ---------------- PTX helpers (sm_80-compatible only) ----------------
__device__ __forceinline__ uint32_t smem_u32(const void* p) {
    uint32_t a;
    asm("{ .reg .u64 t; cvta.to.shared.u64 t, %1; cvt.u32.u64 %0, t; }" : "=r"(a) : "l"(p));
    return a;
}
__device__ __forceinline__ void cpasync16(uint32_t dst, const void* src) {
    asm volatile("cp.async.cg.shared.global [%0], [%1], 16;" :: "r"(dst), "l"(src));
}
#define CP_COMMIT() asm volatile("cp.async.commit_group;")
#define CP_WAIT(n)  asm volatile("cp.async.wait_group %0;" :: "n"(n))

#define LDSM_X4(r, addr) \
    asm volatile("ldmatrix.sync.aligned.m8n8.x4.shared.b16 {%0,%1,%2,%3}, [%4];" \
        : "=r"((r)[0]), "=r"((r)[1]), "=r"((r)[2]), "=r"((r)[3]) : "r"(addr))

__device__ __forceinline__ void mma16816h(float* c, const uint32_t* a, uint32_t b0, uint32_t b1) {
    asm volatile(
        "mma.sync.aligned.m16n8k16.row.col.f32.f16.f16.f32 "
        "{%0,%1,%2,%3}, {%4,%5,%6,%7}, {%8,%9}, {%0,%1,%2,%3};"
        : "+f"(c[0]), "+f"(c[1]), "+f"(c[2]), "+f"(c[3])
        : "r"(a[0]), "r"(a[1]), "r"(a[2]), "r"(a[3]), "r"(b0), "r"(b1));
}

__device__ __forceinline__ uint32_t h2_bits(__half2 h) {
    uint32_t u;
    memcpy(&u, &h, 4);
    return u;
}

// ---------------- K1: point feature moments (float4-vectorized, 4 pts/iter) ----------------
__global__ void pstats_kernel(const float* __restrict__ points, int n_pts) {
    float s[44];
#pragma unroll
    for (int i = 0; i < 44; i++) s[i] = 0.f;
    int gid = blockIdx.x * blockDim.x + threadIdx.x;
    int stride = gridDim.x * blockDim.x;
    int nchunk = n_pts >> 2;
    for (int ch = gid; ch < nchunk; ch += stride) {
        const float4* p4 = (const float4*)(points + (size_t)ch * 36);
        float f36[36];
#pragma unroll
        for (int j = 0; j < 9; j++) {
            float4 v = __ldg(&p4[j]);
            f36[4 * j] = v.x; f36[4 * j + 1] = v.y;
            f36[4 * j + 2] = v.z; f36[4 * j + 3] = v.w;
        }
#pragma unroll
        for (int k = 0; k < 4; k++) {
            const float* f = f36 + 9 * k + 1;
#pragma unroll
            for (int j = 0; j < 8; j++) s[j] += f[j];
            int idx = 8;
#pragma unroll
            for (int j = 0; j < 8; j++)
#pragma unroll
                for (int k2 = j; k2 < 8; k2++) s[idx++] += f[j] * f[k2];
        }
    }
    for (int p = (nchunk << 2) + gid; p < n_pts; p += stride) {
        const float* pt = points + (size_t)p * 9;
        float f[8];
#pragma unroll
        for (int j = 0; j < 8; j++) f[j] = __ldg(&pt[1 + j]);
#pragma unroll
        for (int j = 0; j < 8; j++) s[j] += f[j];
        int idx = 8;
#pragma unroll
        for (int j = 0; j < 8; j++)
#pragma unroll
            for (int k = j; k < 8; k++) s[idx++] += f[j] * f[k];
    }
#pragma unroll
    for (int i = 0; i < 44; i++)
#pragma unroll
        for (int o = 16; o > 0; o >>= 1) s[i] += __shfl_down_sync(0xffffffffu, s[i], o);
    __shared__ float part[8][44];
    int lane = threadIdx.x & 31, w = threadIdx.x >> 5;
    if (lane == 0)
#pragma unroll
        for (int i = 0; i < 44; i++) part[w][i] = s[i];
    __syncthreads();
    if (threadIdx.x < 44) {
        float t = 0.f;
#pragma unroll
        for (int w2 = 0; w2 < 8; w2++) t += part[w2][threadIdx.x];
        atomicAdd(&ACC0[threadIdx.x], t);
    }
}

// ---------------- K2: fold BN0 ----------------
__global__ void fin0_kernel(const float* __restrict__ lin0_w,
                            const float* __restrict__ g0,
                            const float* __restrict__ b0, float inv_n) {
    int c = threadIdx.x;
    float Ef[8];
#pragma unroll
    for (int j = 0; j < 8; j++) Ef[j] = ACC0[j] * inv_n;
    float w[8];
#pragma unroll
    for (int j = 0; j < 8; j++) w[j] = lin0_w[c * 8 + j];
    float m0 = 0.f;
#pragma unroll
    for (int j = 0; j < 8; j++) m0 += w[j] * Ef[j];
    float e2 = 0.f;
    int idx = 8;
#pragma unroll
    for (int j = 0; j < 8; j++)
#pragma unroll
        for (int k = j; k < 8; k++) {
            float t = w[j] * w[k] * (ACC0[idx] * inv_n);
            e2 += (k == j) ? t : 2.f * t;
            idx++;
        }
    float v0 = fmaxf(e2 - m0 * m0, 0.f);
    float scl = g0[c] * rsqrtf(v0 + BN_EPS);
    g_scale0[c] = scl;
    g_bias0[c] = b0[c] - m0 * scl;
}

// ---------------- K3: per-point compute + half2 scatter-add (R13 version) ----------------
__global__ void scatter_kernel(const float* __restrict__ points,
                               const int* __restrict__ pmc,
                               const float* __restrict__ lin0_w, int n_pts) {
    __shared__ float Wt[8][C64];
    __shared__ float sc[C64], bi[C64];
    int tid = threadIdx.x;
    if (tid < C64) { sc[tid] = g_scale0[tid]; bi[tid] = g_bias0[tid]; }
    for (int i = tid; i < 512; i += blockDim.x) {
        int c = i >> 3, j = i & 7;
        Wt[j][c] = lin0_w[i];
    }
    __syncthreads();
    int lane = tid & 31;
    int gw = blockIdx.x * (blockDim.x >> 5) + (tid >> 5);
    int nw = gridDim.x * (blockDim.x >> 5);
    for (int p = gw; p < n_pts; p += nw) {
        int pillar = __ldg(&pmc[p]);
        const float* pt = points + (size_t)p * 9;
        float f[8];
#pragma unroll
        for (int j = 0; j < 8; j++) f[j] = __ldg(&pt[1 + j]);
        int zb = (int)floorf((f[5] + 4.0f) * 4.0f);
        zb = min(max(zb, 0), NBINS - 1);
        size_t base = ((size_t)pillar * NBINS + zb) * C64;
        int c0 = lane * 2;
        float v0 = Wt[0][c0] * f[0], v1 = Wt[0][c0 + 1] * f[0];
#pragma unroll
        for (int j = 1; j < 8; j++) {
            v0 = fmaf(Wt[j][c0], f[j], v0);
            v1 = fmaf(Wt[j][c0 + 1], f[j], v1);
        }
        v0 = fmaxf(fmaf(v0, sc[c0], bi[c0]), 0.f);
        v1 = fmaxf(fmaf(v1, sc[c0 + 1], bi[c0 + 1]), 0.f);
        atomicAdd((__half2*)(g_sums + base + c0), __floats2half2_rn(v0, v1));
        if (lane == 0) atomicAdd(&g_cnt[(size_t)pillar * NBINS + zb], 1.0f);
    }
}

// ---------------- K4: means (+sparse_feat) -> fp16 A; skip empty reads ----------------
__global__ void normsplit_kernel(const float* __restrict__ sparse_feat) {
    size_t i4 = (size_t)blockIdx.x * blockDim.x + threadIdx.x;
    if (i4 >= (size_t)SEGS * C64 / 4) return;
    size_t seg = i4 >> 4;
    float c = g_cnt[seg];
    float4 v = make_float4(0.f, 0.f, 0.f, 0.f);
    if (c > 0.5f) {
        uint2 raw = ((const uint2*)g_sums)[i4];
        __half2 h0, h1;
        memcpy(&h0, &raw.x, 4);
        memcpy(&h1, &raw.y, 4);
        float2 a = __half22float2(h0);
        float2 b = __half22float2(h1);
        float inv = 1.0f / c;
        int pillar = (int)(seg >> 5);
        int cc = (int)(i4 & 15) * 4;
        float4 sf = *(const float4*)(sparse_feat + (size_t)pillar * C64 + cc);
        v.x = fmaf(a.x, inv, sf.x);
        v.y = fmaf(a.y, inv, sf.y);
        v.z = fmaf(b.x, inv, sf.z);
        v.w = fmaf(b.y, inv, sf.w);
    }
    uint32_t p0 = h2_bits(__floats2half2_rn(v.x, v.y));
    uint32_t p1 = h2_bits(__floats2half2_rn(v.z, v.w));
    ((uint2*)g_Ah)[i4] = make_uint2(p0, p1);
}

// ---------------- K4b: round w1 AND w2 to fp16 (merged) ----------------
#define W1_Q (HID * INF / 4)
#define W2_Q (C64 * HID / 4)
__global__ void wconv_kernel(const float* __restrict__ w1, const float* __restrict__ w2) {
    int i4 = blockIdx.x * blockDim.x + threadIdx.x;
    if (i4 < W1_Q) {
        float4 v = ((const float4*)w1)[i4];
        uint32_t p0 = h2_bits(__floats2half2_rn(v.x, v.y));
        uint32_t p1 = h2_bits(__floats2half2_rn(v.z, v.w));
        ((uint2*)g_Wh)[i4] = make_uint2(p0, p1);
    } else if (i4 < W1_Q + W2_Q) {
        int j4 = i4 - W1_Q;
        float4 v = ((const float4*)w2)[j4];
        uint32_t p0 = h2_bits(__floats2half2_rn(v.x, v.y));
        uint32_t p1 = h2_bits(__floats2half2_rn(v.z, v.w));
        ((uint2*)g_W2h)[j4] = make_uint2(p0, p1);
    }
}

// ---------------- K5: occupied mask + n ----------------
__global__ void mask_kernel() {
    int p = blockIdx.x * (blockDim.x >> 5) + (threadIdx.x >> 5);
    int lane = threadIdx.x & 31;
    if (p >= NSP) return;
    float c = g_cnt[(size_t)p * NBINS + lane];
    unsigned bal = __ballot_sync(0xffffffffu, c > 0.5f);
    if (lane == 0) {
        float mk = (__popc(bal) >= 2) ? 1.f : 0.f;
        g_mask[p] = mk;
        atomicAdd(NACC, mk);
    }
}

// ---------------- K6: GEMM1 via mma.sync fp16, single term ----------------
#define KC     32
#define PITCH  80
#define STG_A  (128 * PITCH)         // 10240
#define STG_W  (256 * PITCH)         // 20480
#define STG_BYTES (STG_A + STG_W)    // 30720
#define SMEM_G1 (4 * STG_BYTES)      // 122880
#define NST    64

__device__ __forceinline__ void g1_load_stage(uint32_t sb, int s, int m0, int n0, int tid) {
    if (s < NST) {
        int k0 = s * KC;
        uint32_t buf = sb + (uint32_t)(s & 3) * STG_BYTES;
#pragma unroll
        for (int i = 0; i < 2; i++) {
            int id = tid + i * 256;
            int row = id >> 2, c = id & 3;
            cpasync16(buf + row * PITCH + c * 16,
                      g_Ah + (size_t)(m0 + row) * INF + k0 + c * 8);
        }
#pragma unroll
        for (int i = 0; i < 4; i++) {
            int id = tid + i * 256;
            int row = id >> 2, c = id & 3;
            cpasync16(buf + STG_A + row * PITCH + c * 16,
                      g_Wh + (size_t)(n0 + row) * INF + k0 + c * 8);
        }
    }
    CP_COMMIT();
}

__global__ __launch_bounds__(256, 1) void gemm1_mma_kernel() {
    extern __shared__ char smem[];
    uint32_t sb = smem_u32(smem);
    const int tid = threadIdx.x;
    const int w = tid >> 5, l = tid & 31;
    const int m0 = blockIdx.y * 128;
    const int n0 = blockIdx.x * 256;
    const int wm = (w >> 2) * 64;
    const int wn = (w & 3) * 64;

    float acc[4][8][4];
#pragma unroll
    for (int i = 0; i < 4; i++)
#pragma unroll
        for (int j = 0; j < 8; j++)
#pragma unroll
            for (int k = 0; k < 4; k++) acc[i][j][k] = 0.f;

    g1_load_stage(sb, 0, m0, n0, tid);
    g1_load_stage(sb, 1, m0, n0, tid);
    g1_load_stage(sb, 2, m0, n0, tid);

    const uint32_t aoff = (uint32_t)((wm + (l & 15)) * PITCH + ((l >> 4) & 1) * 16);
    const uint32_t bhoff = (uint32_t)(STG_A + (wn + (l & 15)) * PITCH + ((l >> 4) & 1) * 16);

#pragma unroll 1
    for (int s = 0; s < NST; s++) {
        CP_WAIT(2);
        __syncthreads();
        g1_load_stage(sb, s + 3, m0, n0, tid);
        uint32_t buf = sb + (uint32_t)(s & 3) * STG_BYTES;
#pragma unroll
        for (int h = 0; h < 2; h++) {
            uint32_t af[4][4], bh[4][4];
#pragma unroll
            for (int mt = 0; mt < 4; mt++)
                LDSM_X4(af[mt], buf + aoff + mt * 16 * PITCH + h * 32);
#pragma unroll
            for (int bt = 0; bt < 4; bt++)
                LDSM_X4(bh[bt], buf + bhoff + bt * 16 * PITCH + h * 32);
#pragma unroll
            for (int mt = 0; mt < 4; mt++)
#pragma unroll
                for (int bt = 0; bt < 4; bt++) {
                    mma16816h(acc[mt][bt * 2 + 0], af[mt], bh[bt][0], bh[bt][2]);
                    mma16816h(acc[mt][bt * 2 + 1], af[mt], bh[bt][1], bh[bt][3]);
                }
        }
    }

    // epilogue: fp16 x1 store + fused masked column stats (BN1, f32)
    const int r0 = l >> 2;
    const int cc = (l & 3) * 2;
    float msk[4][2];
#pragma unroll
    for (int mt = 0; mt < 4; mt++) {
        msk[mt][0] = g_mask[m0 + wm + mt * 16 + r0];
        msk[mt][1] = g_mask[m0 + wm + mt * 16 + r0 + 8];
    }
#pragma unroll
    for (int nt = 0; nt < 8; nt++) {
        float s0 = 0.f, q0 = 0.f, s1 = 0.f, q1 = 0.f;
#pragma unroll
        for (int mt = 0; mt < 4; mt++) {
            size_t row = (size_t)(m0 + wm + mt * 16 + r0);
            size_t col = (size_t)(n0 + wn + nt * 8 + cc);
            *(__half2*)(g_x1h + row * HID + col) =
                __floats2half2_rn(acc[mt][nt][0], acc[mt][nt][1]);
            *(__half2*)(g_x1h + (row + 8) * HID + col) =
                __floats2half2_rn(acc[mt][nt][2], acc[mt][nt][3]);
            float a0 = acc[mt][nt][0], a1 = acc[mt][nt][1];
            float a2 = acc[mt][nt][2], a3 = acc[mt][nt][3];
            s0 += msk[mt][0] * a0 + msk[mt][1] * a2;
            q0 += msk[mt][0] * a0 * a0 + msk[mt][1] * a2 * a2;
            s1 += msk[mt][0] * a1 + msk[mt][1] * a3;
            q1 += msk[mt][0] * a1 * a1 + msk[mt][1] * a3 * a3;
        }
#pragma unroll
        for (int o = 4; o <= 16; o <<= 1) {
            s0 += __shfl_xor_sync(0xffffffffu, s0, o);
            q0 += __shfl_xor_sync(0xffffffffu, q0, o);
            s1 += __shfl_xor_sync(0xffffffffu, s1, o);
            q1 += __shfl_xor_sync(0xffffffffu, q1, o);
        }
        if (r0 == 0) {
            int col = n0 + wn + nt * 8 + cc;
            atomicAdd(&S1ACC[col], s0);
            atomicAdd(&Q1ACC[col], q0);
            atomicAdd(&S1ACC[col + 1], s1);
            atomicAdd(&Q1ACC[col + 1], q1);
        }
    }
}

__global__ void fin1_kernel(const float* __restrict__ g1, const float* __restrict__ b1) {
    int c = threadIdx.x;
    float n = fmaxf(*NACC, 1.f);
    float m = S1ACC[c] / n;
    float v = fmaxf(Q1ACC[c] / n - m * m, 0.f);
    float scl = g1[c] * rsqrtf(v + BN_EPS);
    g_scale1[c] = scl;
    g_bias1[c] = b1[c] - m * scl;
}

// ---------------- K8: GEMM2 via mma.sync fp16 + fused BN2 stats ----------------
#define G2_PITCH  80
#define G2_STG_A  (256 * G2_PITCH)    // 20480
#define G2_BPITCH 2064
#define G2_SMEM_B (C64 * G2_BPITCH)   // 132096
#define G2_SMEM   (2 * G2_STG_A + G2_SMEM_B)  // 173056
#define G2_NST    (HID / KC)          // 32

__global__ __launch_bounds__(256, 1) void gemm2_mma_kernel() {
    extern __shared__ char smem[];
    uint32_t sb = smem_u32(smem);
    uint32_t sbB = sb + 2 * G2_STG_A;
    const int tid = threadIdx.x;
    const int w = tid >> 5, l = tid & 31;
    const int m0 = blockIdx.x * 256;
    const int wm = (w >> 1) * 64;
    const int wn = (w & 1) * 32;

#pragma unroll
    for (int i = 0; i < 32; i++) {
        int id = tid + i * 256;
        int row = id >> 7, c = id & 127;
        cpasync16(sbB + row * G2_BPITCH + c * 16, g_W2h + (size_t)row * HID + c * 8);
    }
    CP_COMMIT();

    float acc[4][4][4];
#pragma unroll
    for (int i = 0; i < 4; i++)
#pragma unroll
        for (int j = 0; j < 4; j++)
#pragma unroll
            for (int k = 0; k < 4; k++) acc[i][j][k] = 0.f;

    const size_t arow = (size_t)(m0 + tid);
    uint4 areg[4];
#pragma unroll
    for (int c = 0; c < 4; c++)
        areg[c] = *(const uint4*)(g_x1h + arow * HID + c * 8);

    const uint32_t aoff = (uint32_t)((wm + (l & 15)) * G2_PITCH + ((l >> 4) & 1) * 16);
    const uint32_t boff = (uint32_t)((wn + (l & 15)) * G2_BPITCH + ((l >> 4) & 1) * 16);

    CP_WAIT(0);
    __syncthreads();

#pragma unroll 1
    for (int s = 0; s < G2_NST; s++) {
        int kt = s * KC;
        uint32_t buf = sb + (uint32_t)(s & 1) * G2_STG_A;
#pragma unroll
        for (int c = 0; c < 4; c++) {
            int kg = kt + c * 8;
            float4 sc0 = *(const float4*)(g_scale1 + kg);
            float4 sc1 = *(const float4*)(g_scale1 + kg + 4);
            float4 bi0 = *(const float4*)(g_bias1 + kg);
            float4 bi1 = *(const float4*)(g_bias1 + kg + 4);
            const uint32_t* hp = (const uint32_t*)&areg[c];
            uint4 outv;
            uint32_t* op = (uint32_t*)&outv;
            float scs[8] = {sc0.x, sc0.y, sc0.z, sc0.w, sc1.x, sc1.y, sc1.z, sc1.w};
            float bis[8] = {bi0.x, bi0.y, bi0.z, bi0.w, bi1.x, bi1.y, bi1.z, bi1.w};
#pragma unroll
            for (int q = 0; q < 4; q++) {
                __half2 hv;
                memcpy(&hv, &hp[q], 4);
                float2 f = __half22float2(hv);
                f.x = fmaxf(fmaf(f.x, scs[2 * q], bis[2 * q]), 0.f);
                f.y = fmaxf(fmaf(f.y, scs[2 * q + 1], bis[2 * q + 1]), 0.f);
                op[q] = h2_bits(__floats2half2_rn(f.x, f.y));
            }
            *(uint4*)(smem + (size_t)(s & 1) * G2_STG_A + tid * G2_PITCH + c * 16) = outv;
        }
        __syncthreads();
        if (s + 1 < G2_NST) {
#pragma unroll
            for (int c = 0; c < 4; c++)
                areg[c] = *(const uint4*)(g_x1h + arow * HID + (s + 1) * KC + c * 8);
        }
#pragma unroll
        for (int h = 0; h < 2; h++) {
            uint32_t af[4][4], bf[2][4];
#pragma unroll
            for (int mt = 0; mt < 4; mt++)
                LDSM_X4(af[mt], buf + aoff + mt * 16 * G2_PITCH + h * 32);
#pragma unroll
            for (int bt = 0; bt < 2; bt++)
                LDSM_X4(bf[bt], sbB + boff + bt * 16 * G2_BPITCH + s * 64 + h * 32);
#pragma unroll
            for (int mt = 0; mt < 4; mt++)
#pragma unroll
                for (int bt = 0; bt < 2; bt++) {
                    mma16816h(acc[mt][bt * 2 + 0], af[mt], bf[bt][0], bf[bt][2]);
                    mma16816h(acc[mt][bt * 2 + 1], af[mt], bf[bt][1], bf[bt][3]);
                }
        }
        __syncthreads();
    }

    const int r0 = l >> 2;
    const int cc = (l & 3) * 2;
    float msk[4][2];
#pragma unroll
    for (int mt = 0; mt < 4; mt++) {
        msk[mt][0] = g_mask[m0 + wm + mt * 16 + r0];
        msk[mt][1] = g_mask[m0 + wm + mt * 16 + r0 + 8];
    }
#pragma unroll
    for (int nt = 0; nt < 4; nt++) {
        float s0 = 0.f, q0 = 0.f, s1 = 0.f, q1 = 0.f;
#pragma unroll
        for (int mt = 0; mt < 4; mt++) {
            size_t row = (size_t)(m0 + wm + mt * 16 + r0);
            size_t col = (size_t)(wn + nt * 8 + cc);
            *(float2*)(g_x2 + row * C64 + col) =
                make_float2(acc[mt][nt][0], acc[mt][nt][1]);
            *(float2*)(g_x2 + (row + 8) * C64 + col) =
                make_float2(acc[mt][nt][2], acc[mt][nt][3]);
            float a0 = acc[mt][nt][0], a1 = acc[mt][nt][1];
            float a2 = acc[mt][nt][2], a3 = acc[mt][nt][3];
            s0 += msk[mt][0] * a0 + msk[mt][1] * a2;
            q0 += msk[mt][0] * a0 * a0 + msk[mt][1] * a2 * a2;
            s1 += msk[mt][0] * a1 + msk[mt][1] * a3;
            q1 += msk[mt][0] * a1 * a1 + msk[mt][1] * a3 * a3;
        }
#pragma unroll
        for (int o = 4; o <= 16; o <<= 1) {
            s0 += __shfl_xor_sync(0xffffffffu, s0, o);
            q0 += __shfl_xor_sync(0xffffffffu, q0, o);
            s1 += __shfl_xor_sync(0xffffffffu, s1, o);
            q1 += __shfl_xor_sync(0xffffffffu, q1, o);
        }
        if (r0 == 0) {
            int col = wn + nt * 8 + cc;
            atomicAdd(&S2ACC[col], s0);
            atomicAdd(&Q2ACC[col], q0);
            atomicAdd(&S2ACC[col + 1], s1);
            atomicAdd(&Q2ACC[col + 1], q1);
        }
    }
}

__global__ void fin2_kernel(const float* __restrict__ g2, const float* __restrict__ b2) {
    int c = threadIdx.x;
    float n = fmaxf(*NACC, 1.f);
    float m = S2ACC[c] / n;
    float v = fmaxf(Q2ACC[c] / n - m * m, 0.f);
    float scl = g2[c] * rsqrtf(v + BN_EPS);
    g_scale2[c] = scl;
    g_bias2[c] = b2[c] - m * scl;
}

// ---------------- K10: output (float4-vectorized) ----------------
__global__ void final_kernel(const float* __restrict__ sparse_feat, float* __restrict__ out) {
    int i4 = blockIdx.x * blockDim.x + threadIdx.x;
    if (i4 < NSP * C64 / 4) {
        int p = i4 >> 4;
        int cc = (i4 & 15) * 4;
        float mk = g_mask[p];
        float4 sf = ((const float4*)sparse_feat)[i4];
        float4 x = ((const float4*)g_x2)[i4];
        float4 sc = *(const float4*)(g_scale2 + cc);
        float4 bi = *(const float4*)(g_bias2 + cc);
        float4 o;
        o.x = sf.x + mk * fmaxf(fmaf(sc.x, x.x, bi.x), 0.f);
        o.y = sf.y + mk * fmaxf(fmaf(sc.y, x.y, bi.y), 0.f);
        o.z = sf.z + mk * fmaxf(fmaf(sc.z, x.z, bi.z), 0.f);
        o.w = sf.w + mk * fmaxf(fmaf(sc.w, x.w, bi.w), 0.f);
        ((float4*)out)[i4] = o;
    }
}

// ---------------- launch ----------------
extern "C" void kernel_launch(void* const* d_in, const int* in_sizes, int n_in,
                              void* d_out, int out_size) {
    const float* points = (const float*)d_in[0];
    const float* sparse = (const float*)d_in[1];
    const float* lin0_w = (const float*)d_in[2];
    const float* bn0_g = (const float*)d_in[3];
    const float* bn0_b = (const float*)d_in[4];
    const float* w1 = (const float*)d_in[5];
    const float* bn1_g = (const float*)d_in[6];
    const float* bn1_b = (const float*)d_in[7];
    const float* w2 = (const float*)d_in[8];
    const float* bn2_g = (const float*)d_in[9];
    const float* bn2_b = (const float*)d_in[10];
    const int* pmc = (const int*)d_in[11];
    float* out = (float*)d_out;
    int n_pts = in_sizes[0] / 9;

    cudaFuncSetAttribute(gemm1_mma_kernel, cudaFuncAttributeMaxDynamicSharedMemorySize, SMEM_G1);
    cudaFuncSetAttribute(gemm2_mma_kernel, cudaFuncAttributeMaxDynamicSharedMemorySize, G2_SMEM);

    void *p_sums, *p_cnt, *p_acc;
    cudaGetSymbolAddress(&p_sums, g_sums);
    cudaGetSymbolAddress(&p_cnt, g_cnt);
    cudaGetSymbolAddress(&p_acc, g_accbuf);
    cudaMemsetAsync(p_sums, 0, sizeof(g_sums));
    cudaMemsetAsync(p_cnt, 0, sizeof(g_cnt));
    cudaMemsetAsync(p_acc, 0, sizeof(g_accbuf));

    pstats_kernel<<<256, 256>>>(points, n_pts);
    fin0_kernel<<<1, 64>>>(lin0_w, bn0_g, bn0_b, 1.0f / (float)n_pts);
    wconv_kernel<<<(W1_Q + W2_Q + 255) / 256, 256>>>(w1, w2);
    scatter_kernel<<<1024, 256>>>(points, pmc, lin0_w, n_pts);
    normsplit_kernel<<<(SEGS * C64 / 4) / 256, 256>>>(sparse);
    mask_kernel<<<NSP / 8, 256>>>();
    gemm1_mma_kernel<<<dim3(HID / 256, NSP / 128), 256, SMEM_G1>>>();
    fin1_kernel<<<1, HID>>>(bn1_g, bn1_b);
    gemm2_mma_kernel<<<NSP / 256, 256, G2_SMEM>>>();
    fin2_kernel<<<1, 64>>>(bn2_g, bn2_b);
    final_kernel<<<(NSP * C64 / 4 + 255) / 256, 256>>>(sparse, out);
}

// round 16
// speedup vs baseline: 1.0095x; 1.0047x over previous
#include <cuda_runtime.h>
#include <cuda_bf16.h>
#include <cuda_fp16.h>
#include <cstdint>

// ---------------- problem constants ----------------
#define C64   64
#define NBINS 32
#define NSP   32768
#define SEGS  (NSP * NBINS)        // 1048576
#define INF   2048                 // IN = C*NBINS
#define HID   1024
#define BN_EPS 1e-3f

// ---------------- device scratch (static; no allocs) ----------------
__device__ __align__(16) __half g_sums[(size_t)SEGS * C64];          // 128 MB half accum
__device__ __align__(16) float g_cnt[SEGS];                          // 4 MB
__device__ __align__(16) __half g_Ah[(size_t)NSP * INF];             // 128 MB fp16(A)
__device__ __align__(16) __half g_Wh[(size_t)HID * INF];             // 4 MB fp16(w1)
__device__ __align__(16) __half g_x1h[(size_t)NSP * HID];            // 64 MB fp16(x1)
__device__ __align__(16) __half g_W2h[(size_t)C64 * HID];            // 128 KB fp16(w2)
__device__ __align__(16) float g_x2[(size_t)NSP * C64];              // 8 MB
__device__ __align__(16) float g_mask[NSP];
__device__ __align__(16) float g_scale0[C64], g_bias0[C64];
__device__ __align__(16) float g_scale1[HID], g_bias1[HID];

#define ACC_N (44 + 2 * HID + 2 * C64 + 1)
__device__ __align__(16) float g_accbuf[ACC_N];
#define ACC0  (g_accbuf)
#define S1ACC (g_accbuf + 44)
#define Q1ACC (g_accbuf + 44 + HID)
#define S2ACC (g_accbuf + 44 + 2 * HID)
#define Q2ACC (g_accbuf + 44 + 2 * HID + C64)
#define NACC  (g_accbuf + 44 + 2 * HID + 2 * C64)

// ---------------- PTX helpers (sm_80-compatible only) ----------------
__device__ __forceinline__ uint32_t smem_u32(const void* p) {
    uint32_t a;
    asm("{ .reg .u64 t; cvta.to.shared.u64 t, %1; cvt.u32.u64 %0, t; }" : "=r"(a) : "l"(p));
    return a;
}
__device__ __forceinline__ void cpasync16(uint32_t dst, const void* src) {
    asm volatile("cp.async.cg.shared.global [%0], [%1], 16;" :: "r"(dst), "l"(src));
}
#define CP_COMMIT() asm volatile("cp.async.commit_group;")
#define CP_WAIT(n)  asm volatile("cp.async.wait_group %0;" :: "n"(n))

#define LDSM_X4(r, addr) \
    asm volatile("ldmatrix.sync.aligned.m8n8.x4.shared.b16 {%0,%1,%2,%3}, [%4];" \
        : "=r"((r)[0]), "=r"((r)[1]), "=r"((r)[2]), "=r"((r)[3]) : "r"(addr))

__device__ __forceinline__ void mma16816h(float* c, const uint32_t* a, uint32_t b0, uint32_t b1) {
    asm volatile(
        "mma.sync.aligned.m16n8k16.row.col.f32.f16.f16.f32 "
        "{%0,%1,%2,%3}, {%4,%5,%6,%7}, {%8,%9}, {%0,%1,%2,%3};"
        : "+f"(c[0]), "+f"(c[1]), "+f"(c[2]), "+f"(c[3])
        : "r"(a[0]), "r"(a[1]), "r"(a[2]), "r"(a[3]), "r"(b0), "r"(b1));
}

__device__ __forceinline__ uint32_t h2_bits(__half2 h) {
    uint32_t u;
    memcpy(&u, &h, 4);
    return u;
}

// ---------------- K1: point feature moments (float4-vectorized, 4 pts/iter) ----------------
__global__ void pstats_kernel(const float* __restrict__ points, int n_pts) {
    float s[44];
#pragma unroll
    for (int i = 0; i < 44; i++) s[i] = 0.f;
    int gid = blockIdx.x * blockDim.x + threadIdx.x;
    int stride = gridDim.x * blockDim.x;
    int nchunk = n_pts >> 2;
    for (int ch = gid; ch < nchunk; ch += stride) {
        const float4* p4 = (const float4*)(points + (size_t)ch * 36);
        float f36[36];
#pragma unroll
        for (int j = 0; j < 9; j++) {
            float4 v = __ldg(&p4[j]);
            f36[4 * j] = v.x; f36[4 * j + 1] = v.y;
            f36[4 * j + 2] = v.z; f36[4 * j + 3] = v.w;
        }
#pragma unroll
        for (int k = 0; k < 4; k++) {
            const float* f = f36 + 9 * k + 1;
#pragma unroll
            for (int j = 0; j < 8; j++) s[j] += f[j];
            int idx = 8;
#pragma unroll
            for (int j = 0; j < 8; j++)
#pragma unroll
                for (int k2 = j; k2 < 8; k2++) s[idx++] += f[j] * f[k2];
        }
    }
    for (int p = (nchunk << 2) + gid; p < n_pts; p += stride) {
        const float* pt = points + (size_t)p * 9;
        float f[8];
#pragma unroll
        for (int j = 0; j < 8; j++) f[j] = __ldg(&pt[1 + j]);
#pragma unroll
        for (int j = 0; j < 8; j++) s[j] += f[j];
        int idx = 8;
#pragma unroll
        for (int j = 0; j < 8; j++)
#pragma unroll
            for (int k = j; k < 8; k++) s[idx++] += f[j] * f[k];
    }
#pragma unroll
    for (int i = 0; i < 44; i++)
#pragma unroll
        for (int o = 16; o > 0; o >>= 1) s[i] += __shfl_down_sync(0xffffffffu, s[i], o);
    __shared__ float part[8][44];
    int lane = threadIdx.x & 31, w = threadIdx.x >> 5;
    if (lane == 0)
#pragma unroll
        for (int i = 0; i < 44; i++) part[w][i] = s[i];
    __syncthreads();
    if (threadIdx.x < 44) {
        float t = 0.f;
#pragma unroll
        for (int w2 = 0; w2 < 8; w2++) t += part[w2][threadIdx.x];
        atomicAdd(&ACC0[threadIdx.x], t);
    }
}

// ---------------- K2: fold BN0 ----------------
__global__ void fin0_kernel(const float* __restrict__ lin0_w,
                            const float* __restrict__ g0,
                            const float* __restrict__ b0, float inv_n) {
    int c = threadIdx.x;
    float Ef[8];
#pragma unroll
    for (int j = 0; j < 8; j++) Ef[j] = ACC0[j] * inv_n;
    float w[8];
#pragma unroll
    for (int j = 0; j < 8; j++) w[j] = lin0_w[c * 8 + j];
    float m0 = 0.f;
#pragma unroll
    for (int j = 0; j < 8; j++) m0 += w[j] * Ef[j];
    float e2 = 0.f;
    int idx = 8;
#pragma unroll
    for (int j = 0; j < 8; j++)
#pragma unroll
        for (int k = j; k < 8; k++) {
            float t = w[j] * w[k] * (ACC0[idx] * inv_n);
            e2 += (k == j) ? t : 2.f * t;
            idx++;
        }
    float v0 = fmaxf(e2 - m0 * m0, 0.f);
    float scl = g0[c] * rsqrtf(v0 + BN_EPS);
    g_scale0[c] = scl;
    g_bias0[c] = b0[c] - m0 * scl;
}

// ---------------- K3: per-point compute + half2 scatter-add ----------------
__global__ void scatter_kernel(const float* __restrict__ points,
                               const int* __restrict__ pmc,
                               const float* __restrict__ lin0_w, int n_pts) {
    __shared__ float Wt[8][C64];
    __shared__ float sc[C64], bi[C64];
    int tid = threadIdx.x;
    if (tid < C64) { sc[tid] = g_scale0[tid]; bi[tid] = g_bias0[tid]; }
    for (int i = tid; i < 512; i += blockDim.x) {
        int c = i >> 3, j = i & 7;
        Wt[j][c] = lin0_w[i];
    }
    __syncthreads();
    int lane = tid & 31;
    int gw = blockIdx.x * (blockDim.x >> 5) + (tid >> 5);
    int nw = gridDim.x * (blockDim.x >> 5);
    for (int p = gw; p < n_pts; p += nw) {
        int pillar = __ldg(&pmc[p]);
        const float* pt = points + (size_t)p * 9;
        float f[8];
#pragma unroll
        for (int j = 0; j < 8; j++) f[j] = __ldg(&pt[1 + j]);
        int zb = (int)floorf((f[5] + 4.0f) * 4.0f);
        zb = min(max(zb, 0), NBINS - 1);
        size_t base = ((size_t)pillar * NBINS + zb) * C64;
        int c0 = lane * 2;
        float v0 = Wt[0][c0] * f[0], v1 = Wt[0][c0 + 1] * f[0];
#pragma unroll
        for (int j = 1; j < 8; j++) {
            v0 = fmaf(Wt[j][c0], f[j], v0);
            v1 = fmaf(Wt[j][c0 + 1], f[j], v1);
        }
        v0 = fmaxf(fmaf(v0, sc[c0], bi[c0]), 0.f);
        v1 = fmaxf(fmaf(v1, sc[c0 + 1], bi[c0 + 1]), 0.f);
        atomicAdd((__half2*)(g_sums + base + c0), __floats2half2_rn(v0, v1));
        if (lane == 0) atomicAdd(&g_cnt[(size_t)pillar * NBINS + zb], 1.0f);
    }
}

// ---------------- K4: means (+sparse_feat) -> fp16 A; skip empty reads ----------------
__global__ void normsplit_kernel(const float* __restrict__ sparse_feat) {
    size_t i4 = (size_t)blockIdx.x * blockDim.x + threadIdx.x;
    if (i4 >= (size_t)SEGS * C64 / 4) return;
    size_t seg = i4 >> 4;
    float c = g_cnt[seg];
    float4 v = make_float4(0.f, 0.f, 0.f, 0.f);
    if (c > 0.5f) {
        uint2 raw = ((const uint2*)g_sums)[i4];
        __half2 h0, h1;
        memcpy(&h0, &raw.x, 4);
        memcpy(&h1, &raw.y, 4);
        float2 a = __half22float2(h0);
        float2 b = __half22float2(h1);
        float inv = 1.0f / c;
        int pillar = (int)(seg >> 5);
        int cc = (int)(i4 & 15) * 4;
        float4 sf = *(const float4*)(sparse_feat + (size_t)pillar * C64 + cc);
        v.x = fmaf(a.x, inv, sf.x);
        v.y = fmaf(a.y, inv, sf.y);
        v.z = fmaf(b.x, inv, sf.z);
        v.w = fmaf(b.y, inv, sf.w);
    }
    uint32_t p0 = h2_bits(__floats2half2_rn(v.x, v.y));
    uint32_t p1 = h2_bits(__floats2half2_rn(v.z, v.w));
    ((uint2*)g_Ah)[i4] = make_uint2(p0, p1);
}

// ---------------- K4b: round w1 AND w2 to fp16 (merged) ----------------
#define W1_Q (HID * INF / 4)
#define W2_Q (C64 * HID / 4)
__global__ void wconv_kernel(const float* __restrict__ w1, const float* __restrict__ w2) {
    int i4 = blockIdx.x * blockDim.x + threadIdx.x;
    if (i4 < W1_Q) {
        float4 v = ((const float4*)w1)[i4];
        uint32_t p0 = h2_bits(__floats2half2_rn(v.x, v.y));
        uint32_t p1 = h2_bits(__floats2half2_rn(v.z, v.w));
        ((uint2*)g_Wh)[i4] = make_uint2(p0, p1);
    } else if (i4 < W1_Q + W2_Q) {
        int j4 = i4 - W1_Q;
        float4 v = ((const float4*)w2)[j4];
        uint32_t p0 = h2_bits(__floats2half2_rn(v.x, v.y));
        uint32_t p1 = h2_bits(__floats2half2_rn(v.z, v.w));
        ((uint2*)g_W2h)[j4] = make_uint2(p0, p1);
    }
}

// ---------------- K5: occupied mask + n ----------------
__global__ void mask_kernel() {
    int p = blockIdx.x * (blockDim.x >> 5) + (threadIdx.x >> 5);
    int lane = threadIdx.x & 31;
    if (p >= NSP) return;
    float c = g_cnt[(size_t)p * NBINS + lane];
    unsigned bal = __ballot_sync(0xffffffffu, c > 0.5f);
    if (lane == 0) {
        float mk = (__popc(bal) >= 2) ? 1.f : 0.f;
        g_mask[p] = mk;
        atomicAdd(NACC, mk);
    }
}

// ---------------- K6: GEMM1 via mma.sync fp16, single term ----------------
#define KC     32
#define PITCH  80
#define STG_A  (128 * PITCH)         // 10240
#define STG_W  (256 * PITCH)         // 20480
#define STG_BYTES (STG_A + STG_W)    // 30720
#define SMEM_G1 (4 * STG_BYTES)      // 122880
#define NST    64

__device__ __forceinline__ void g1_load_stage(uint32_t sb, int s, int m0, int n0, int tid) {
    if (s < NST) {
        int k0 = s * KC;
        uint32_t buf = sb + (uint32_t)(s & 3) * STG_BYTES;
#pragma unroll
        for (int i = 0; i < 2; i++) {
            int id = tid + i * 256;
            int row = id >> 2, c = id & 3;
            cpasync16(buf + row * PITCH + c * 16,
                      g_Ah + (size_t)(m0 + row) * INF + k0 + c * 8);
        }
#pragma unroll
        for (int i = 0; i < 4; i++) {
            int id = tid + i * 256;
            int row = id >> 2, c = id & 3;
            cpasync16(buf + STG_A + row * PITCH + c * 16,
                      g_Wh + (size_t)(n0 + row) * INF + k0 + c * 8);
        }
    }
    CP_COMMIT();
}

__global__ __launch_bounds__(256, 1) void gemm1_mma_kernel() {
    extern __shared__ char smem[];
    uint32_t sb = smem_u32(smem);
    const int tid = threadIdx.x;
    const int w = tid >> 5, l = tid & 31;
    const int m0 = blockIdx.y * 128;
    const int n0 = blockIdx.x * 256;
    const int wm = (w >> 2) * 64;
    const int wn = (w & 3) * 64;

    float acc[4][8][4];
#pragma unroll
    for (int i = 0; i < 4; i++)
#pragma unroll
        for (int j = 0; j < 8; j++)
#pragma unroll
            for (int k = 0; k < 4; k++) acc[i][j][k] = 0.f;

    g1_load_stage(sb, 0, m0, n0, tid);
    g1_load_stage(sb, 1, m0, n0, tid);
    g1_load_stage(sb, 2, m0, n0, tid);

    const uint32_t aoff = (uint32_t)((wm + (l & 15)) * PITCH + ((l >> 4) & 1) * 16);
    const uint32_t bhoff = (uint32_t)(STG_A + (wn + (l & 15)) * PITCH + ((l >> 4) & 1) * 16);

#pragma unroll 1
    for (int s = 0; s < NST; s++) {
        CP_WAIT(2);
        __syncthreads();
        g1_load_stage(sb, s + 3, m0, n0, tid);
        uint32_t buf = sb + (uint32_t)(s & 3) * STG_BYTES;
#pragma unroll
        for (int h = 0; h < 2; h++) {
            uint32_t af[4][4], bh[4][4];
#pragma unroll
            for (int mt = 0; mt < 4; mt++)
                LDSM_X4(af[mt], buf + aoff + mt * 16 * PITCH + h * 32);
#pragma unroll
            for (int bt = 0; bt < 4; bt++)
                LDSM_X4(bh[bt], buf + bhoff + bt * 16 * PITCH + h * 32);
#pragma unroll
            for (int mt = 0; mt < 4; mt++)
#pragma unroll
                for (int bt = 0; bt < 4; bt++) {
                    mma16816h(acc[mt][bt * 2 + 0], af[mt], bh[bt][0], bh[bt][2]);
                    mma16816h(acc[mt][bt * 2 + 1], af[mt], bh[bt][1], bh[bt][3]);
                }
        }
    }

    // epilogue: fp16 x1 store + fused masked column stats (BN1, f32)
    const int r0 = l >> 2;
    const int cc = (l & 3) * 2;
    float msk[4][2];
#pragma unroll
    for (int mt = 0; mt < 4; mt++) {
        msk[mt][0] = g_mask[m0 + wm + mt * 16 + r0];
        msk[mt][1] = g_mask[m0 + wm + mt * 16 + r0 + 8];
    }
#pragma unroll
    for (int nt = 0; nt < 8; nt++) {
        float s0 = 0.f, q0 = 0.f, s1 = 0.f, q1 = 0.f;
#pragma unroll
        for (int mt = 0; mt < 4; mt++) {
            size_t row = (size_t)(m0 + wm + mt * 16 + r0);
            size_t col = (size_t)(n0 + wn + nt * 8 + cc);
            *(__half2*)(g_x1h + row * HID + col) =
                __floats2half2_rn(acc[mt][nt][0], acc[mt][nt][1]);
            *(__half2*)(g_x1h + (row + 8) * HID + col) =
                __floats2half2_rn(acc[mt][nt][2], acc[mt][nt][3]);
            float a0 = acc[mt][nt][0], a1 = acc[mt][nt][1];
            float a2 = acc[mt][nt][2], a3 = acc[mt][nt][3];
            s0 += msk[mt][0] * a0 + msk[mt][1] * a2;
            q0 += msk[mt][0] * a0 * a0 + msk[mt][1] * a2 * a2;
            s1 += msk[mt][0] * a1 + msk[mt][1] * a3;
            q1 += msk[mt][0] * a1 * a1 + msk[mt][1] * a3 * a3;
        }
#pragma unroll
        for (int o = 4; o <= 16; o <<= 1) {
            s0 += __shfl_xor_sync(0xffffffffu, s0, o);
            q0 += __shfl_xor_sync(0xffffffffu, q0, o);
            s1 += __shfl_xor_sync(0xffffffffu, s1, o);
            q1 += __shfl_xor_sync(0xffffffffu, q1, o);
        }
        if (r0 == 0) {
            int col = n0 + wn + nt * 8 + cc;
            atomicAdd(&S1ACC[col], s0);
            atomicAdd(&Q1ACC[col], q0);
            atomicAdd(&S1ACC[col + 1], s1);
            atomicAdd(&Q1ACC[col + 1], q1);
        }
    }
}

__global__ void fin1_kernel(const float* __restrict__ g1, const float* __restrict__ b1) {
    int c = threadIdx.x;
    float n = fmaxf(*NACC, 1.f);
    float m = S1ACC[c] / n;
    float v = fmaxf(Q1ACC[c] / n - m * m, 0.f);
    float scl = g1[c] * rsqrtf(v + BN_EPS);
    g_scale1[c] = scl;
    g_bias1[c] = b1[c] - m * scl;
}

// ---------------- K8: GEMM2 via mma.sync fp16 + fused BN2 stats ----------------
#define G2_PITCH  80
#define G2_STG_A  (256 * G2_PITCH)    // 20480
#define G2_BPITCH 2064
#define G2_SMEM_B (C64 * G2_BPITCH)   // 132096
#define G2_SMEM   (2 * G2_STG_A + G2_SMEM_B)  // 173056
#define G2_NST    (HID / KC)          // 32

__global__ __launch_bounds__(256, 1) void gemm2_mma_kernel() {
    extern __shared__ char smem[];
    uint32_t sb = smem_u32(smem);
    uint32_t sbB = sb + 2 * G2_STG_A;
    const int tid = threadIdx.x;
    const int w = tid >> 5, l = tid & 31;
    const int m0 = blockIdx.x * 256;
    const int wm = (w >> 1) * 64;
    const int wn = (w & 1) * 32;

#pragma unroll
    for (int i = 0; i < 32; i++) {
        int id = tid + i * 256;
        int row = id >> 7, c = id & 127;
        cpasync16(sbB + row * G2_BPITCH + c * 16, g_W2h + (size_t)row * HID + c * 8);
    }
    CP_COMMIT();

    float acc[4][4][4];
#pragma unroll
    for (int i = 0; i < 4; i++)
#pragma unroll
        for (int j = 0; j < 4; j++)
#pragma unroll
            for (int k = 0; k < 4; k++) acc[i][j][k] = 0.f;

    const size_t arow = (size_t)(m0 + tid);
    uint4 areg[4];
#pragma unroll
    for (int c = 0; c < 4; c++)
        areg[c] = *(const uint4*)(g_x1h + arow * HID + c * 8);

    const uint32_t aoff = (uint32_t)((wm + (l & 15)) * G2_PITCH + ((l >> 4) & 1) * 16);
    const uint32_t boff = (uint32_t)((wn + (l & 15)) * G2_BPITCH + ((l >> 4) & 1) * 16);

    CP_WAIT(0);
    __syncthreads();

#pragma unroll 1
    for (int s = 0; s < G2_NST; s++) {
        int kt = s * KC;
        uint32_t buf = sb + (uint32_t)(s & 1) * G2_STG_A;
#pragma unroll
        for (int c = 0; c < 4; c++) {
            int kg = kt + c * 8;
            float4 sc0 = *(const float4*)(g_scale1 + kg);
            float4 sc1 = *(const float4*)(g_scale1 + kg + 4);
            float4 bi0 = *(const float4*)(g_bias1 + kg);
            float4 bi1 = *(const float4*)(g_bias1 + kg + 4);
            const uint32_t* hp = (const uint32_t*)&areg[c];
            uint4 outv;
            uint32_t* op = (uint32_t*)&outv;
            float scs[8] = {sc0.x, sc0.y, sc0.z, sc0.w, sc1.x, sc1.y, sc1.z, sc1.w};
            float bis[8] = {bi0.x, bi0.y, bi0.z, bi0.w, bi1.x, bi1.y, bi1.z, bi1.w};
#pragma unroll
            for (int q = 0; q < 4; q++) {
                __half2 hv;
                memcpy(&hv, &hp[q], 4);
                float2 f = __half22float2(hv);
                f.x = fmaxf(fmaf(f.x, scs[2 * q], bis[2 * q]), 0.f);
                f.y = fmaxf(fmaf(f.y, scs[2 * q + 1], bis[2 * q + 1]), 0.f);
                op[q] = h2_bits(__floats2half2_rn(f.x, f.y));
            }
            *(uint4*)(smem + (size_t)(s & 1) * G2_STG_A + tid * G2_PITCH + c * 16) = outv;
        }
        __syncthreads();
        if (s + 1 < G2_NST) {
#pragma unroll
            for (int c = 0; c < 4; c++)
                areg[c] = *(const uint4*)(g_x1h + arow * HID + (s + 1) * KC + c * 8);
        }
#pragma unroll
        for (int h = 0; h < 2; h++) {
            uint32_t af[4][4], bf[2][4];
#pragma unroll
            for (int mt = 0; mt < 4; mt++)
                LDSM_X4(af[mt], buf + aoff + mt * 16 * G2_PITCH + h * 32);
#pragma unroll
            for (int bt = 0; bt < 2; bt++)
                LDSM_X4(bf[bt], sbB + boff + bt * 16 * G2_BPITCH + s * 64 + h * 32);
#pragma unroll
            for (int mt = 0; mt < 4; mt++)
#pragma unroll
                for (int bt = 0; bt < 2; bt++) {
                    mma16816h(acc[mt][bt * 2 + 0], af[mt], bf[bt][0], bf[bt][2]);
                    mma16816h(acc[mt][bt * 2 + 1], af[mt], bf[bt][1], bf[bt][3]);
                }
        }
        __syncthreads();
    }

    const int r0 = l >> 2;
    const int cc = (l & 3) * 2;
    float msk[4][2];
#pragma unroll
    for (int mt = 0; mt < 4; mt++) {
        msk[mt][0] = g_mask[m0 + wm + mt * 16 + r0];
        msk[mt][1] = g_mask[m0 + wm + mt * 16 + r0 + 8];
    }
#pragma unroll
    for (int nt = 0; nt < 4; nt++) {
        float s0 = 0.f, q0 = 0.f, s1 = 0.f, q1 = 0.f;
#pragma unroll
        for (int mt = 0; mt < 4; mt++) {
            size_t row = (size_t)(m0 + wm + mt * 16 + r0);
            size_t col = (size_t)(wn + nt * 8 + cc);
            *(float2*)(g_x2 + row * C64 + col) =
                make_float2(acc[mt][nt][0], acc[mt][nt][1]);
            *(float2*)(g_x2 + (row + 8) * C64 + col) =
                make_float2(acc[mt][nt][2], acc[mt][nt][3]);
            float a0 = acc[mt][nt][0], a1 = acc[mt][nt][1];
            float a2 = acc[mt][nt][2], a3 = acc[mt][nt][3];
            s0 += msk[mt][0] * a0 + msk[mt][1] * a2;
            q0 += msk[mt][0] * a0 * a0 + msk[mt][1] * a2 * a2;
            s1 += msk[mt][0] * a1 + msk[mt][1] * a3;
            q1 += msk[mt][0] * a1 * a1 + msk[mt][1] * a3 * a3;
        }
#pragma unroll
        for (int o = 4; o <= 16; o <<= 1) {
            s0 += __shfl_xor_sync(0xffffffffu, s0, o);
            q0 += __shfl_xor_sync(0xffffffffu, q0, o);
            s1 += __shfl_xor_sync(0xffffffffu, s1, o);
            q1 += __shfl_xor_sync(0xffffffffu, q1, o);
        }
        if (r0 == 0) {
            int col = wn + nt * 8 + cc;
            atomicAdd(&S2ACC[col], s0);
            atomicAdd(&Q2ACC[col], q0);
            atomicAdd(&S2ACC[col + 1], s1);
            atomicAdd(&Q2ACC[col + 1], q1);
        }
    }
}

// ---------------- K10: output (float4) with fused BN2 finalize ----------------
__global__ void final_kernel(const float* __restrict__ sparse_feat,
                             const float* __restrict__ g2,
                             const float* __restrict__ b2,
                             float* __restrict__ out) {
    __shared__ float ssc[C64], sbi[C64];
    if (threadIdx.x < C64) {
        int c = threadIdx.x;
        float n = fmaxf(*NACC, 1.f);
        float m = S2ACC[c] / n;
        float v = fmaxf(Q2ACC[c] / n - m * m, 0.f);
        float scl = g2[c] * rsqrtf(v + BN_EPS);
        ssc[c] = scl;
        sbi[c] = b2[c] - m * scl;
    }
    __syncthreads();
    int i4 = blockIdx.x * blockDim.x + threadIdx.x;
    if (i4 < NSP * C64 / 4) {
        int p = i4 >> 4;
        int cc = (i4 & 15) * 4;
        float mk = g_mask[p];
        float4 sf = ((const float4*)sparse_feat)[i4];
        float4 x = ((const float4*)g_x2)[i4];
        float4 o;
        o.x = sf.x + mk * fmaxf(fmaf(ssc[cc + 0], x.x, sbi[cc + 0]), 0.f);
        o.y = sf.y + mk * fmaxf(fmaf(ssc[cc + 1], x.y, sbi[cc + 1]), 0.f);
        o.z = sf.z + mk * fmaxf(fmaf(ssc[cc + 2], x.z, sbi[cc + 2]), 0.f);
        o.w = sf.w + mk * fmaxf(fmaf(ssc[cc + 3], x.w, sbi[cc + 3]), 0.f);
        ((float4*)out)[i4] = o;
    }
}

// ---------------- launch ----------------
extern "C" void kernel_launch(void* const* d_in, const int* in_sizes, int n_in,
                              void* d_out, int out_size) {
    const float* points = (const float*)d_in[0];
    const float* sparse = (const float*)d_in[1];
    const float* lin0_w = (const float*)d_in[2];
    const float* bn0_g = (const float*)d_in[3];
    const float* bn0_b = (const float*)d_in[4];
    const float* w1 = (const float*)d_in[5];
    const float* bn1_g = (const float*)d_in[6];
    const float* bn1_b = (const float*)d_in[7];
    const float* w2 = (const float*)d_in[8];
    const float* bn2_g = (const float*)d_in[9];
    const float* bn2_b = (const float*)d_in[10];
    const int* pmc = (const int*)d_in[11];
    float* out = (float*)d_out;
    int n_pts = in_sizes[0] / 9;

    cudaFuncSetAttribute(gemm1_mma_kernel, cudaFuncAttributeMaxDynamicSharedMemorySize, SMEM_G1);
    cudaFuncSetAttribute(gemm2_mma_kernel, cudaFuncAttributeMaxDynamicSharedMemorySize, G2_SMEM);

    void *p_sums, *p_cnt, *p_acc;
    cudaGetSymbolAddress(&p_sums, g_sums);
    cudaGetSymbolAddress(&p_cnt, g_cnt);
    cudaGetSymbolAddress(&p_acc, g_accbuf);
    cudaMemsetAsync(p_sums, 0, sizeof(g_sums));
    cudaMemsetAsync(p_cnt, 0, sizeof(g_cnt));
    cudaMemsetAsync(p_acc, 0, sizeof(g_accbuf));

    pstats_kernel<<<256, 256>>>(points, n_pts);
    fin0_kernel<<<1, 64>>>(lin0_w, bn0_g, bn0_b, 1.0f / (float)n_pts);
    wconv_kernel<<<(W1_Q + W2_Q + 255) / 256, 256>>>(w1, w2);
    scatter_kernel<<<1024, 256>>>(points, pmc, lin0_w, n_pts);
    normsplit_kernel<<<(SEGS * C64 / 4) / 256, 256>>>(sparse);
    mask_kernel<<<NSP / 8, 256>>>();
    gemm1_mma_kernel<<<dim3(HID / 256, NSP / 128), 256, SMEM_G1>>>();
    fin1_kernel<<<1, HID>>>(bn1_g, bn1_b);
    gemm2_mma_kernel<<<NSP / 256, 256, G2_SMEM>>>();
    final_kernel<<<(NSP * C64 / 4 + 255) / 256, 256>>>(sparse, bn2_g, bn2_b, out);
}

// round 17
// speedup vs baseline: 1.0138x; 1.0043x over previous
#include <cuda_runtime.h>
#include <cuda_bf16.h>
#include <cuda_fp16.h>
#include <cstdint>

// ---------------- problem constants ----------------
#define C64   64
#define NBINS 32
#define NSP   32768
#define SEGS  (NSP * NBINS)        // 1048576
#define INF   2048                 // IN = C*NBINS
#define HID   1024
#define BN_EPS 1e-3f

// ---------------- device scratch (static; no allocs) ----------------
__device__ __align__(16) __half g_sums[(size_t)SEGS * C64];          // 128 MB half accum
__device__ __align__(16) float g_cnt[SEGS];                          // 4 MB
__device__ __align__(16) __half g_Ah[(size_t)NSP * INF];             // 128 MB fp16(A)
__device__ __align__(16) __half g_Wh[(size_t)HID * INF];             // 4 MB fp16(w1)
__device__ __align__(16) __half g_x1h[(size_t)NSP * HID];            // 64 MB fp16(x1)
__device__ __align__(16) __half g_W2h[(size_t)C64 * HID];            // 128 KB fp16(w2)
__device__ __align__(16) float g_x2[(size_t)NSP * C64];              // 8 MB
__device__ __align__(16) float g_mask[NSP];
__device__ __align__(16) float g_scale0[C64], g_bias0[C64];

#define ACC_N (44 + 2 * HID + 2 * C64 + 1)
__device__ __align__(16) float g_accbuf[ACC_N];
#define ACC0  (g_accbuf)
#define S1ACC (g_accbuf + 44)
#define Q1ACC (g_accbuf + 44 + HID)
#define S2ACC (g_accbuf + 44 + 2 * HID)
#define Q2ACC (g_accbuf + 44 + 2 * HID + C64)
#define NACC  (g_accbuf + 44 + 2 * HID + 2 * C64)

// ---------------- PTX helpers (sm_80-compatible only) ----------------
__device__ __forceinline__ uint32_t smem_u32(const void* p) {
    uint32_t a;
    asm("{ .reg .u64 t; cvta.to.shared.u64 t, %1; cvt.u32.u64 %0, t; }" : "=r"(a) : "l"(p));
    return a;
}
__device__ __forceinline__ void cpasync16(uint32_t dst, const void* src) {
    asm volatile("cp.async.cg.shared.global [%0], [%1], 16;" :: "r"(dst), "l"(src));
}
#define CP_COMMIT() asm volatile("cp.async.commit_group;")
#define CP_WAIT(n)  asm volatile("cp.async.wait_group %0;" :: "n"(n))

#define LDSM_X4(r, addr) \
    asm volatile("ldmatrix.sync.aligned.m8n8.x4.shared.b16 {%0,%1,%2,%3}, [%4];" \
        : "=r"((r)[0]), "=r"((r)[1]), "=r"((r)[2]), "=r"((r)[3]) : "r"(addr))

__device__ __forceinline__ void mma16816h(float* c, const uint32_t* a, uint32_t b0, uint32_t b1) {
    asm volatile(
        "mma.sync.aligned.m16n8k16.row.col.f32.f16.f16.f32 "
        "{%0,%1,%2,%3}, {%4,%5,%6,%7}, {%8,%9}, {%0,%1,%2,%3};"
        : "+f"(c[0]), "+f"(c[1]), "+f"(c[2]), "+f"(c[3])
        : "r"(a[0]), "r"(a[1]), "r"(a[2]), "r"(a[3]), "r"(b0), "r"(b1));
}

__device__ __forceinline__ uint32_t h2_bits(__half2 h) {
    uint32_t u;
    memcpy(&u, &h, 4);
    return u;
}

// ---------------- K1: point feature moments (float4-vectorized, 4 pts/iter) ----------------
__global__ void pstats_kernel(const float* __restrict__ points, int n_pts) {
    float s[44];
#pragma unroll
    for (int i = 0; i < 44; i++) s[i] = 0.f;
    int gid = blockIdx.x * blockDim.x + threadIdx.x;
    int stride = gridDim.x * blockDim.x;
    int nchunk = n_pts >> 2;
    for (int ch = gid; ch < nchunk; ch += stride) {
        const float4* p4 = (const float4*)(points + (size_t)ch * 36);
        float f36[36];
#pragma unroll
        for (int j = 0; j < 9; j++) {
            float4 v = __ldg(&p4[j]);
            f36[4 * j] = v.x; f36[4 * j + 1] = v.y;
            f36[4 * j + 2] = v.z; f36[4 * j + 3] = v.w;
        }
#pragma unroll
        for (int k = 0; k < 4; k++) {
            const float* f = f36 + 9 * k + 1;
#pragma unroll
            for (int j = 0; j < 8; j++) s[j] += f[j];
            int idx = 8;
#pragma unroll
            for (int j = 0; j < 8; j++)
#pragma unroll
                for (int k2 = j; k2 < 8; k2++) s[idx++] += f[j] * f[k2];
        }
    }
    for (int p = (nchunk << 2) + gid; p < n_pts; p += stride) {
        const float* pt = points + (size_t)p * 9;
        float f[8];
#pragma unroll
        for (int j = 0; j < 8; j++) f[j] = __ldg(&pt[1 + j]);
#pragma unroll
        for (int j = 0; j < 8; j++) s[j] += f[j];
        int idx = 8;
#pragma unroll
        for (int j = 0; j < 8; j++)
#pragma unroll
            for (int k = j; k < 8; k++) s[idx++] += f[j] * f[k];
    }
#pragma unroll
    for (int i = 0; i < 44; i++)
#pragma unroll
        for (int o = 16; o > 0; o >>= 1) s[i] += __shfl_down_sync(0xffffffffu, s[i], o);
    __shared__ float part[8][44];
    int lane = threadIdx.x & 31, w = threadIdx.x >> 5;
    if (lane == 0)
#pragma unroll
        for (int i = 0; i < 44; i++) part[w][i] = s[i];
    __syncthreads();
    if (threadIdx.x < 44) {
        float t = 0.f;
#pragma unroll
        for (int w2 = 0; w2 < 8; w2++) t += part[w2][threadIdx.x];
        atomicAdd(&ACC0[threadIdx.x], t);
    }
}

// ---------------- K2: fold BN0 ----------------
__global__ void fin0_kernel(const float* __restrict__ lin0_w,
                            const float* __restrict__ g0,
                            const float* __restrict__ b0, float inv_n) {
    int c = threadIdx.x;
    float Ef[8];
#pragma unroll
    for (int j = 0; j < 8; j++) Ef[j] = ACC0[j] * inv_n;
    float w[8];
#pragma unroll
    for (int j = 0; j < 8; j++) w[j] = lin0_w[c * 8 + j];
    float m0 = 0.f;
#pragma unroll
    for (int j = 0; j < 8; j++) m0 += w[j] * Ef[j];
    float e2 = 0.f;
    int idx = 8;
#pragma unroll
    for (int j = 0; j < 8; j++)
#pragma unroll
        for (int k = j; k < 8; k++) {
            float t = w[j] * w[k] * (ACC0[idx] * inv_n);
            e2 += (k == j) ? t : 2.f * t;
            idx++;
        }
    float v0 = fmaxf(e2 - m0 * m0, 0.f);
    float scl = g0[c] * rsqrtf(v0 + BN_EPS);
    g_scale0[c] = scl;
    g_bias0[c] = b0[c] - m0 * scl;
}

// ---------------- K3: per-point compute + half2 scatter-add ----------------
__global__ void scatter_kernel(const float* __restrict__ points,
                               const int* __restrict__ pmc,
                               const float* __restrict__ lin0_w, int n_pts) {
    __shared__ float Wt[8][C64];
    __shared__ float sc[C64], bi[C64];
    int tid = threadIdx.x;
    if (tid < C64) { sc[tid] = g_scale0[tid]; bi[tid] = g_bias0[tid]; }
    for (int i = tid; i < 512; i += blockDim.x) {
        int c = i >> 3, j = i & 7;
        Wt[j][c] = lin0_w[i];
    }
    __syncthreads();
    int lane = tid & 31;
    int gw = blockIdx.x * (blockDim.x >> 5) + (tid >> 5);
    int nw = gridDim.x * (blockDim.x >> 5);
    for (int p = gw; p < n_pts; p += nw) {
        int pillar = __ldg(&pmc[p]);
        const float* pt = points + (size_t)p * 9;
        float f[8];
#pragma unroll
        for (int j = 0; j < 8; j++) f[j] = __ldg(&pt[1 + j]);
        int zb = (int)floorf((f[5] + 4.0f) * 4.0f);
        zb = min(max(zb, 0), NBINS - 1);
        size_t base = ((size_t)pillar * NBINS + zb) * C64;
        int c0 = lane * 2;
        float v0 = Wt[0][c0] * f[0], v1 = Wt[0][c0 + 1] * f[0];
#pragma unroll
        for (int j = 1; j < 8; j++) {
            v0 = fmaf(Wt[j][c0], f[j], v0);
            v1 = fmaf(Wt[j][c0 + 1], f[j], v1);
        }
        v0 = fmaxf(fmaf(v0, sc[c0], bi[c0]), 0.f);
        v1 = fmaxf(fmaf(v1, sc[c0 + 1], bi[c0 + 1]), 0.f);
        atomicAdd((__half2*)(g_sums + base + c0), __floats2half2_rn(v0, v1));
        if (lane == 0) atomicAdd(&g_cnt[(size_t)pillar * NBINS + zb], 1.0f);
    }
}

// ---------------- K4: means (+sparse_feat) -> fp16 A; skip empty reads ----------------
__global__ void normsplit_kernel(const float* __restrict__ sparse_feat) {
    size_t i4 = (size_t)blockIdx.x * blockDim.x + threadIdx.x;
    if (i4 >= (size_t)SEGS * C64 / 4) return;
    size_t seg = i4 >> 4;
    float c = g_cnt[seg];
    float4 v = make_float4(0.f, 0.f, 0.f, 0.f);
    if (c > 0.5f) {
        uint2 raw = ((const uint2*)g_sums)[i4];
        __half2 h0, h1;
        memcpy(&h0, &raw.x, 4);
        memcpy(&h1, &raw.y, 4);
        float2 a = __half22float2(h0);
        float2 b = __half22float2(h1);
        float inv = 1.0f / c;
        int pillar = (int)(seg >> 5);
        int cc = (int)(i4 & 15) * 4;
        float4 sf = *(const float4*)(sparse_feat + (size_t)pillar * C64 + cc);
        v.x = fmaf(a.x, inv, sf.x);
        v.y = fmaf(a.y, inv, sf.y);
        v.z = fmaf(b.x, inv, sf.z);
        v.w = fmaf(b.y, inv, sf.w);
    }
    uint32_t p0 = h2_bits(__floats2half2_rn(v.x, v.y));
    uint32_t p1 = h2_bits(__floats2half2_rn(v.z, v.w));
    ((uint2*)g_Ah)[i4] = make_uint2(p0, p1);
}

// ---------------- K4b: round w1 AND w2 to fp16 (merged) ----------------
#define W1_Q (HID * INF / 4)
#define W2_Q (C64 * HID / 4)
__global__ void wconv_kernel(const float* __restrict__ w1, const float* __restrict__ w2) {
    int i4 = blockIdx.x * blockDim.x + threadIdx.x;
    if (i4 < W1_Q) {
        float4 v = ((const float4*)w1)[i4];
        uint32_t p0 = h2_bits(__floats2half2_rn(v.x, v.y));
        uint32_t p1 = h2_bits(__floats2half2_rn(v.z, v.w));
        ((uint2*)g_Wh)[i4] = make_uint2(p0, p1);
    } else if (i4 < W1_Q + W2_Q) {
        int j4 = i4 - W1_Q;
        float4 v = ((const float4*)w2)[j4];
        uint32_t p0 = h2_bits(__floats2half2_rn(v.x, v.y));
        uint32_t p1 = h2_bits(__floats2half2_rn(v.z, v.w));
        ((uint2*)g_W2h)[j4] = make_uint2(p0, p1);
    }
}

// ---------------- K5: occupied mask + n ----------------
__global__ void mask_kernel() {
    int p = blockIdx.x * (blockDim.x >> 5) + (threadIdx.x >> 5);
    int lane = threadIdx.x & 31;
    if (p >= NSP) return;
    float c = g_cnt[(size_t)p * NBINS + lane];
    unsigned bal = __ballot_sync(0xffffffffu, c > 0.5f);
    if (lane == 0) {
        float mk = (__popc(bal) >= 2) ? 1.f : 0.f;
        g_mask[p] = mk;
        atomicAdd(NACC, mk);
    }
}

// ---------------- K6: GEMM1 via mma.sync fp16, single term ----------------
#define KC     32
#define PITCH  80
#define STG_A  (128 * PITCH)         // 10240
#define STG_W  (256 * PITCH)         // 20480
#define STG_BYTES (STG_A + STG_W)    // 30720
#define SMEM_G1 (4 * STG_BYTES)      // 122880
#define NST    64

__device__ __forceinline__ void g1_load_stage(uint32_t sb, int s, int m0, int n0, int tid) {
    if (s < NST) {
        int k0 = s * KC;
        uint32_t buf = sb + (uint32_t)(s & 3) * STG_BYTES;
#pragma unroll
        for (int i = 0; i < 2; i++) {
            int id = tid + i * 256;
            int row = id >> 2, c = id & 3;
            cpasync16(buf + row * PITCH + c * 16,
                      g_Ah + (size_t)(m0 + row) * INF + k0 + c * 8);
        }
#pragma unroll
        for (int i = 0; i < 4; i++) {
            int id = tid + i * 256;
            int row = id >> 2, c = id & 3;
            cpasync16(buf + STG_A + row * PITCH + c * 16,
                      g_Wh + (size_t)(n0 + row) * INF + k0 + c * 8);
        }
    }
    CP_COMMIT();
}

__global__ __launch_bounds__(256, 1) void gemm1_mma_kernel() {
    extern __shared__ char smem[];
    uint32_t sb = smem_u32(smem);
    const int tid = threadIdx.x;
    const int w = tid >> 5, l = tid & 31;
    const int m0 = blockIdx.y * 128;
    const int n0 = blockIdx.x * 256;
    const int wm = (w >> 2) * 64;
    const int wn = (w & 3) * 64;

    float acc[4][8][4];
#pragma unroll
    for (int i = 0; i < 4; i++)
#pragma unroll
        for (int j = 0; j < 8; j++)
#pragma unroll
            for (int k = 0; k < 4; k++) acc[i][j][k] = 0.f;

    g1_load_stage(sb, 0, m0, n0, tid);
    g1_load_stage(sb, 1, m0, n0, tid);
    g1_load_stage(sb, 2, m0, n0, tid);

    const uint32_t aoff = (uint32_t)((wm + (l & 15)) * PITCH + ((l >> 4) & 1) * 16);
    const uint32_t bhoff = (uint32_t)(STG_A + (wn + (l & 15)) * PITCH + ((l >> 4) & 1) * 16);

#pragma unroll 1
    for (int s = 0; s < NST; s++) {
        CP_WAIT(2);
        __syncthreads();
        g1_load_stage(sb, s + 3, m0, n0, tid);
        uint32_t buf = sb + (uint32_t)(s & 3) * STG_BYTES;
#pragma unroll
        for (int h = 0; h < 2; h++) {
            uint32_t af[4][4], bh[4][4];
#pragma unroll
            for (int mt = 0; mt < 4; mt++)
                LDSM_X4(af[mt], buf + aoff + mt * 16 * PITCH + h * 32);
#pragma unroll
            for (int bt = 0; bt < 4; bt++)
                LDSM_X4(bh[bt], buf + bhoff + bt * 16 * PITCH + h * 32);
#pragma unroll
            for (int mt = 0; mt < 4; mt++)
#pragma unroll
                for (int bt = 0; bt < 4; bt++) {
                    mma16816h(acc[mt][bt * 2 + 0], af[mt], bh[bt][0], bh[bt][2]);
                    mma16816h(acc[mt][bt * 2 + 1], af[mt], bh[bt][1], bh[bt][3]);
                }
        }
    }

    // epilogue: fp16 x1 store + fused masked column stats (BN1, f32)
    const int r0 = l >> 2;
    const int cc = (l & 3) * 2;
    float msk[4][2];
#pragma unroll
    for (int mt = 0; mt < 4; mt++) {
        msk[mt][0] = g_mask[m0 + wm + mt * 16 + r0];
        msk[mt][1] = g_mask[m0 + wm + mt * 16 + r0 + 8];
    }
#pragma unroll
    for (int nt = 0; nt < 8; nt++) {
        float s0 = 0.f, q0 = 0.f, s1 = 0.f, q1 = 0.f;
#pragma unroll
        for (int mt = 0; mt < 4; mt++) {
            size_t row = (size_t)(m0 + wm + mt * 16 + r0);
            size_t col = (size_t)(n0 + wn + nt * 8 + cc);
            *(__half2*)(g_x1h + row * HID + col) =
                __floats2half2_rn(acc[mt][nt][0], acc[mt][nt][1]);
            *(__half2*)(g_x1h + (row + 8) * HID + col) =
                __floats2half2_rn(acc[mt][nt][2], acc[mt][nt][3]);
            float a0 = acc[mt][nt][0], a1 = acc[mt][nt][1];
            float a2 = acc[mt][nt][2], a3 = acc[mt][nt][3];
            s0 += msk[mt][0] * a0 + msk[mt][1] * a2;
            q0 += msk[mt][0] * a0 * a0 + msk[mt][1] * a2 * a2;
            s1 += msk[mt][0] * a1 + msk[mt][1] * a3;
            q1 += msk[mt][0] * a1 * a1 + msk[mt][1] * a3 * a3;
        }
#pragma unroll
        for (int o = 4; o <= 16; o <<= 1) {
            s0 += __shfl_xor_sync(0xffffffffu, s0, o);
            q0 += __shfl_xor_sync(0xffffffffu, q0, o);
            s1 += __shfl_xor_sync(0xffffffffu, s1, o);
            q1 += __shfl_xor_sync(0xffffffffu, q1, o);
        }
        if (r0 == 0) {
            int col = n0 + wn + nt * 8 + cc;
            atomicAdd(&S1ACC[col], s0);
            atomicAdd(&Q1ACC[col], q0);
            atomicAdd(&S1ACC[col + 1], s1);
            atomicAdd(&Q1ACC[col + 1], q1);
        }
    }
}

// ---------------- K8: GEMM2 via mma.sync fp16 + fused BN1 finalize + BN2 stats ----------------
#define G2_PITCH  80
#define G2_STG_A  (256 * G2_PITCH)    // 20480
#define G2_BPITCH 2064
#define G2_SMEM_B (C64 * G2_BPITCH)   // 132096
#define G2_BN1    (2 * HID * 4)       // 8192: ssc1 + sbi1
#define G2_SMEM   (2 * G2_STG_A + G2_SMEM_B + G2_BN1)  // 181248
#define G2_NST    (HID / KC)          // 32

__global__ __launch_bounds__(256, 1) void gemm2_mma_kernel(const float* __restrict__ g1,
                                                           const float* __restrict__ b1) {
    extern __shared__ char smem[];
    uint32_t sb = smem_u32(smem);
    uint32_t sbB = sb + 2 * G2_STG_A;
    float* ssc1 = (float*)(smem + 2 * G2_STG_A + G2_SMEM_B);
    float* sbi1 = ssc1 + HID;
    const int tid = threadIdx.x;
    const int w = tid >> 5, l = tid & 31;
    const int m0 = blockIdx.x * 256;
    const int wm = (w >> 1) * 64;
    const int wn = (w & 1) * 32;

#pragma unroll
    for (int i = 0; i < 32; i++) {
        int id = tid + i * 256;
        int row = id >> 7, c = id & 127;
        cpasync16(sbB + row * G2_BPITCH + c * 16, g_W2h + (size_t)row * HID + c * 8);
    }
    CP_COMMIT();

    // fused fin1: compute BN1 scale/bias into smem (4 channels per thread)
    {
        float n = fmaxf(*NACC, 1.f);
#pragma unroll
        for (int i = 0; i < 4; i++) {
            int c = tid + i * 256;
            float m = S1ACC[c] / n;
            float v = fmaxf(Q1ACC[c] / n - m * m, 0.f);
            float scl = g1[c] * rsqrtf(v + BN_EPS);
            ssc1[c] = scl;
            sbi1[c] = b1[c] - m * scl;
        }
    }

    float acc[4][4][4];
#pragma unroll
    for (int i = 0; i < 4; i++)
#pragma unroll
        for (int j = 0; j < 4; j++)
#pragma unroll
            for (int k = 0; k < 4; k++) acc[i][j][k] = 0.f;

    const size_t arow = (size_t)(m0 + tid);
    uint4 areg[4];
#pragma unroll
    for (int c = 0; c < 4; c++)
        areg[c] = *(const uint4*)(g_x1h + arow * HID + c * 8);

    const uint32_t aoff = (uint32_t)((wm + (l & 15)) * G2_PITCH + ((l >> 4) & 1) * 16);
    const uint32_t boff = (uint32_t)((wn + (l & 15)) * G2_BPITCH + ((l >> 4) & 1) * 16);

    CP_WAIT(0);
    __syncthreads();

#pragma unroll 1
    for (int s = 0; s < G2_NST; s++) {
        int kt = s * KC;
        uint32_t buf = sb + (uint32_t)(s & 1) * G2_STG_A;
#pragma unroll
        for (int c = 0; c < 4; c++) {
            int kg = kt + c * 8;
            float4 sc0 = *(const float4*)(ssc1 + kg);
            float4 sc1 = *(const float4*)(ssc1 + kg + 4);
            float4 bi0 = *(const float4*)(sbi1 + kg);
            float4 bi1 = *(const float4*)(sbi1 + kg + 4);
            const uint32_t* hp = (const uint32_t*)&areg[c];
            uint4 outv;
            uint32_t* op = (uint32_t*)&outv;
            float scs[8] = {sc0.x, sc0.y, sc0.z, sc0.w, sc1.x, sc1.y, sc1.z, sc1.w};
            float bis[8] = {bi0.x, bi0.y, bi0.z, bi0.w, bi1.x, bi1.y, bi1.z, bi1.w};
#pragma unroll
            for (int q = 0; q < 4; q++) {
                __half2 hv;
                memcpy(&hv, &hp[q], 4);
                float2 f = __half22float2(hv);
                f.x = fmaxf(fmaf(f.x, scs[2 * q], bis[2 * q]), 0.f);
                f.y = fmaxf(fmaf(f.y, scs[2 * q + 1], bis[2 * q + 1]), 0.f);
                op[q] = h2_bits(__floats2half2_rn(f.x, f.y));
            }
            *(uint4*)(smem + (size_t)(s & 1) * G2_STG_A + tid * G2_PITCH + c * 16) = outv;
        }
        __syncthreads();
        if (s + 1 < G2_NST) {
#pragma unroll
            for (int c = 0; c < 4; c++)
                areg[c] = *(const uint4*)(g_x1h + arow * HID + (s + 1) * KC + c * 8);
        }
#pragma unroll
        for (int h = 0; h < 2; h++) {
            uint32_t af[4][4], bf[2][4];
#pragma unroll
            for (int mt = 0; mt < 4; mt++)
                LDSM_X4(af[mt], buf + aoff + mt * 16 * G2_PITCH + h * 32);
#pragma unroll
            for (int bt = 0; bt < 2; bt++)
                LDSM_X4(bf[bt], sbB + boff + bt * 16 * G2_BPITCH + s * 64 + h * 32);
#pragma unroll
            for (int mt = 0; mt < 4; mt++)
#pragma unroll
                for (int bt = 0; bt < 2; bt++) {
                    mma16816h(acc[mt][bt * 2 + 0], af[mt], bf[bt][0], bf[bt][2]);
                    mma16816h(acc[mt][bt * 2 + 1], af[mt], bf[bt][1], bf[bt][3]);
                }
        }
        __syncthreads();
    }

    const int r0 = l >> 2;
    const int cc = (l & 3) * 2;
    float msk[4][2];
#pragma unroll
    for (int mt = 0; mt < 4; mt++) {
        msk[mt][0] = g_mask[m0 + wm + mt * 16 + r0];
        msk[mt][1] = g_mask[m0 + wm + mt * 16 + r0 + 8];
    }
#pragma unroll
    for (int nt = 0; nt < 4; nt++) {
        float s0 = 0.f, q0 = 0.f, s1 = 0.f, q1 = 0.f;
#pragma unroll
        for (int mt = 0; mt < 4; mt++) {
            size_t row = (size_t)(m0 + wm + mt * 16 + r0);
            size_t col = (size_t)(wn + nt * 8 + cc);
            *(float2*)(g_x2 + row * C64 + col) =
                make_float2(acc[mt][nt][0], acc[mt][nt][1]);
            *(float2*)(g_x2 + (row + 8) * C64 + col) =
                make_float2(acc[mt][nt][2], acc[mt][nt][3]);
            float a0 = acc[mt][nt][0], a1 = acc[mt][nt][1];
            float a2 = acc[mt][nt][2], a3 = acc[mt][nt][3];
            s0 += msk[mt][0] * a0 + msk[mt][1] * a2;
            q0 += msk[mt][0] * a0 * a0 + msk[mt][1] * a2 * a2;
            s1 += msk[mt][0] * a1 + msk[mt][1] * a3;
            q1 += msk[mt][0] * a1 * a1 + msk[mt][1] * a3 * a3;
        }
#pragma unroll
        for (int o = 4; o <= 16; o <<= 1) {
            s0 += __shfl_xor_sync(0xffffffffu, s0, o);
            q0 += __shfl_xor_sync(0xffffffffu, q0, o);
            s1 += __shfl_xor_sync(0xffffffffu, s1, o);
            q1 += __shfl_xor_sync(0xffffffffu, q1, o);
        }
        if (r0 == 0) {
            int col = wn + nt * 8 + cc;
            atomicAdd(&S2ACC[col], s0);
            atomicAdd(&Q2ACC[col], q0);
            atomicAdd(&S2ACC[col + 1], s1);
            atomicAdd(&Q2ACC[col + 1], q1);
        }
    }
}

// ---------------- K10: output (float4) with fused BN2 finalize ----------------
__global__ void final_kernel(const float* __restrict__ sparse_feat,
                             const float* __restrict__ g2,
                             const float* __restrict__ b2,
                             float* __restrict__ out) {
    __shared__ float ssc[C64], sbi[C64];
    if (threadIdx.x < C64) {
        int c = threadIdx.x;
        float n = fmaxf(*NACC, 1.f);
        float m = S2ACC[c] / n;
        float v = fmaxf(Q2ACC[c] / n - m * m, 0.f);
        float scl = g2[c] * rsqrtf(v + BN_EPS);
        ssc[c] = scl;
        sbi[c] = b2[c] - m * scl;
    }
    __syncthreads();
    int i4 = blockIdx.x * blockDim.x + threadIdx.x;
    if (i4 < NSP * C64 / 4) {
        int p = i4 >> 4;
        int cc = (i4 & 15) * 4;
        float mk = g_mask[p];
        float4 sf = ((const float4*)sparse_feat)[i4];
        float4 x = ((const float4*)g_x2)[i4];
        float4 o;
        o.x = sf.x + mk * fmaxf(fmaf(ssc[cc + 0], x.x, sbi[cc + 0]), 0.f);
        o.y = sf.y + mk * fmaxf(fmaf(ssc[cc + 1], x.y, sbi[cc + 1]), 0.f);
        o.z = sf.z + mk * fmaxf(fmaf(ssc[cc + 2], x.z, sbi[cc + 2]), 0.f);
        o.w = sf.w + mk * fmaxf(fmaf(ssc[cc + 3], x.w, sbi[cc + 3]), 0.f);
        ((float4*)out)[i4] = o;
    }
}

// ---------------- launch ----------------
extern "C" void kernel_launch(void* const* d_in, const int* in_sizes, int n_in,
                              void* d_out, int out_size) {
    const float* points = (const float*)d_in[0];
    const float* sparse = (const float*)d_in[1];
    const float* lin0_w = (const float*)d_in[2];
    const float* bn0_g = (const float*)d_in[3];
    const float* bn0_b = (const float*)d_in[4];
    const float* w1 = (const float*)d_in[5];
    const float* bn1_g = (const float*)d_in[6];
    const float* bn1_b = (const float*)d_in[7];
    const float* w2 = (const float*)d_in[8];
    const float* bn2_g = (const float*)d_in[9];
    const float* bn2_b = (const float*)d_in[10];
    const int* pmc = (const int*)d_in[11];
    float* out = (float*)d_out;
    int n_pts = in_sizes[0] / 9;

    cudaFuncSetAttribute(gemm1_mma_kernel, cudaFuncAttributeMaxDynamicSharedMemorySize, SMEM_G1);
    cudaFuncSetAttribute(gemm2_mma_kernel, cudaFuncAttributeMaxDynamicSharedMemorySize, G2_SMEM);

    void *p_sums, *p_cnt, *p_acc;
    cudaGetSymbolAddress(&p_sums, g_sums);
    cudaGetSymbolAddress(&p_cnt, g_cnt);
    cudaGetSymbolAddress(&p_acc, g_accbuf);
    cudaMemsetAsync(p_sums, 0, sizeof(g_sums));
    cudaMemsetAsync(p_cnt, 0, sizeof(g_cnt));
    cudaMemsetAsync(p_acc, 0, sizeof(g_accbuf));

    pstats_kernel<<<256, 256>>>(points, n_pts);
    fin0_kernel<<<1, 64>>>(lin0_w, bn0_g, bn0_b, 1.0f / (float)n_pts);
    wconv_kernel<<<(W1_Q + W2_Q + 255) / 256, 256>>>(w1, w2);
    scatter_kernel<<<1024, 256>>>(points, pmc, lin0_w, n_pts);
    normsplit_kernel<<<(SEGS * C64 / 4) / 256, 256>>>(sparse);
    mask_kernel<<<NSP / 8, 256>>>();
    gemm1_mma_kernel<<<dim3(HID / 256, NSP / 128), 256, SMEM_G1>>>();
    gemm2_mma_kernel<<<NSP / 256, 256, G2_SMEM>>>(bn1_g, bn1_b);
    final_kernel<<<(NSP * C64 / 4 + 255) / 256, 256>>>(sparse, bn2_g, bn2_b, out);
}